// round 1
// baseline (speedup 1.0000x reference)
#include <cuda_runtime.h>
#include <cstdio>

// ---------------------------------------------------------------------------
// MultiHeadAttention: B=4, H=16, S=2048, D=1024, dk=64, fp32.
// Pipeline: 3x proj GEMM -> flash attention -> out proj GEMM.
// ---------------------------------------------------------------------------

#define BATCH 4
#define HEADS 16
#define SEQ   2048
#define DMODEL 1024
#define DK    64
#define MROWS (BATCH * SEQ)        // 8192

// Scratch (static device globals; allocation-free per harness rules)
__device__ float g_Q[BATCH * HEADS * SEQ * DK];   // [b][h][s][dk]
__device__ float g_K[BATCH * HEADS * SEQ * DK];
__device__ float g_V[BATCH * HEADS * SEQ * DK];
__device__ float g_O[BATCH * SEQ * DMODEL];       // [b][s][h*dk]

// ---------------------------------------------------------------------------
// SGEMM: C[M=8192, N=1024] = A[M,K=1024] * B[N,K]^T + bias[N]
// Block tile 128x128, K-tile 16, 256 threads, 8x8 per-thread microtile,
// register-staged double-buffered shared memory.
// mode 0: scatter epilogue into [b][h][s][dk] layout (QKV projections)
// mode 1: plain row-major [M,N] (output projection)
// ---------------------------------------------------------------------------
__global__ void __launch_bounds__(256)
gemm_kernel(const float* __restrict__ A, const float* __restrict__ B,
            const float* __restrict__ bias, float* __restrict__ C, int mode)
{
    __shared__ float As[2][16][128];
    __shared__ float Bs[2][16][128];

    const int t  = threadIdx.x;
    const int bm = blockIdx.y * 128;
    const int bn = blockIdx.x * 128;

    const int lr = t >> 2;           // 0..63
    const int lc = (t & 3) << 2;     // 0,4,8,12

    float4 a0, a1, b0, b1;

    const float* Abase = A + (size_t)(bm + lr) * DMODEL + lc;
    const float* Bbase = B + (size_t)(bn + lr) * DMODEL + lc;

    auto LD = [&](int kt) {
        const float* pa = Abase + kt * 16;
        a0 = *(const float4*)pa;
        a1 = *(const float4*)(pa + 64 * DMODEL);
        const float* pb = Bbase + kt * 16;
        b0 = *(const float4*)pb;
        b1 = *(const float4*)(pb + 64 * DMODEL);
    };
    auto ST = [&](int buf) {
        As[buf][lc + 0][lr] = a0.x; As[buf][lc + 1][lr] = a0.y;
        As[buf][lc + 2][lr] = a0.z; As[buf][lc + 3][lr] = a0.w;
        As[buf][lc + 0][lr + 64] = a1.x; As[buf][lc + 1][lr + 64] = a1.y;
        As[buf][lc + 2][lr + 64] = a1.z; As[buf][lc + 3][lr + 64] = a1.w;
        Bs[buf][lc + 0][lr] = b0.x; Bs[buf][lc + 1][lr] = b0.y;
        Bs[buf][lc + 2][lr] = b0.z; Bs[buf][lc + 3][lr] = b0.w;
        Bs[buf][lc + 0][lr + 64] = b1.x; Bs[buf][lc + 1][lr + 64] = b1.y;
        Bs[buf][lc + 2][lr + 64] = b1.z; Bs[buf][lc + 3][lr + 64] = b1.w;
    };

    LD(0); ST(0);
    __syncthreads();

    float acc[8][8];
#pragma unroll
    for (int i = 0; i < 8; ++i)
#pragma unroll
        for (int j = 0; j < 8; ++j) acc[i][j] = 0.f;

    const int ty = t >> 4, tx = t & 15;
    int buf = 0;

    for (int kt = 0; kt < 64; ++kt) {
        if (kt < 63) LD(kt + 1);
#pragma unroll
        for (int kk = 0; kk < 16; ++kk) {
            float ar[8], br[8];
            *(float4*)(ar)     = *(const float4*)&As[buf][kk][ty * 8];
            *(float4*)(ar + 4) = *(const float4*)&As[buf][kk][ty * 8 + 4];
            *(float4*)(br)     = *(const float4*)&Bs[buf][kk][tx * 8];
            *(float4*)(br + 4) = *(const float4*)&Bs[buf][kk][tx * 8 + 4];
#pragma unroll
            for (int i = 0; i < 8; ++i)
#pragma unroll
                for (int j = 0; j < 8; ++j)
                    acc[i][j] += ar[i] * br[j];
        }
        if (kt < 63) ST(buf ^ 1);
        __syncthreads();
        buf ^= 1;
    }

    // Epilogue
#pragma unroll
    for (int i = 0; i < 8; ++i) {
        const int m = bm + ty * 8 + i;
#pragma unroll
        for (int j = 0; j < 8; ++j) {
            const int n = bn + tx * 8 + j;
            const float v = acc[i][j] + bias[n];
            if (mode == 0) {
                const int bb = m >> 11;        // m / 2048
                const int s  = m & 2047;
                const int h  = n >> 6;         // n / 64
                const int dd = n & 63;
                C[(((size_t)(bb * HEADS + h) * SEQ + s) << 6) + dd] = v;
            } else {
                C[(size_t)m * DMODEL + n] = v;
            }
        }
    }
}

// ---------------------------------------------------------------------------
// Flash attention (fp32): one block per (b, h, 64-query tile).
// smem: Qs[d][m], Ks[d][n], Vs[j][dv], Ps[j][m], all stride PAD=68.
// Thread grid 16x16; each thread owns 4 q rows x 4 cols.
// Online softmax with shfl reductions over the 16-lane row group.
// ---------------------------------------------------------------------------
#define PAD 68
#define FLASH_SMEM (4 * 64 * PAD * 4)

__global__ void __launch_bounds__(256)
flash_kernel()
{
    extern __shared__ float sm[];
    float* Qs = sm;                 // [64][PAD]  Qs[d*PAD + m]
    float* Ks = Qs + 64 * PAD;      // [64][PAD]  Ks[d*PAD + n]
    float* Vs = Ks + 64 * PAD;      // [64][PAD]  Vs[j*PAD + dv]
    float* Ps = Vs + 64 * PAD;      // [64][PAD]  Ps[j*PAD + m]

    const int t  = threadIdx.x;
    const int b  = blockIdx.z;
    const int h  = blockIdx.y;
    const int qb = blockIdx.x * 64;

    const float* Qg = g_Q + ((size_t)(b * HEADS + h) * SEQ) * DK;
    const float* Kg = g_K + ((size_t)(b * HEADS + h) * SEQ) * DK;
    const float* Vg = g_V + ((size_t)(b * HEADS + h) * SEQ) * DK;

    const int lrow = t >> 2;            // 0..63
    const int dbase = (t & 3) << 4;     // 0,16,32,48

    // Load Q tile (transposed, scaled by 1/sqrt(dk) = 0.125)
    {
        const float4* qr = (const float4*)(Qg + (size_t)(qb + lrow) * DK + dbase);
#pragma unroll
        for (int i = 0; i < 4; ++i) {
            float4 v = qr[i];
            const int d = dbase + i * 4;
            Qs[(d + 0) * PAD + lrow] = v.x * 0.125f;
            Qs[(d + 1) * PAD + lrow] = v.y * 0.125f;
            Qs[(d + 2) * PAD + lrow] = v.z * 0.125f;
            Qs[(d + 3) * PAD + lrow] = v.w * 0.125f;
        }
    }

    const int tx = t & 15, ty = t >> 4;
    const int m0 = ty * 4, n0 = tx * 4;

    float rm[4], rl[4], o[4][4];
#pragma unroll
    for (int i = 0; i < 4; ++i) {
        rm[i] = -1e30f; rl[i] = 0.f;
#pragma unroll
        for (int j = 0; j < 4; ++j) o[i][j] = 0.f;
    }

    for (int kv = 0; kv < SEQ / 64; ++kv) {
        const int kb = kv * 64;
        // Load K (transposed) and V (natural)
        {
            const float4* kr = (const float4*)(Kg + (size_t)(kb + lrow) * DK + dbase);
            const float4* vr = (const float4*)(Vg + (size_t)(kb + lrow) * DK + dbase);
#pragma unroll
            for (int i = 0; i < 4; ++i) {
                float4 v = kr[i];
                const int d = dbase + i * 4;
                Ks[(d + 0) * PAD + lrow] = v.x;
                Ks[(d + 1) * PAD + lrow] = v.y;
                Ks[(d + 2) * PAD + lrow] = v.z;
                Ks[(d + 3) * PAD + lrow] = v.w;
                *(float4*)&Vs[lrow * PAD + dbase + i * 4] = vr[i];
            }
        }
        __syncthreads();

        // S = Q K^T (scores), 4x4 per thread
        float acc[4][4];
#pragma unroll
        for (int i = 0; i < 4; ++i)
#pragma unroll
            for (int j = 0; j < 4; ++j) acc[i][j] = 0.f;

#pragma unroll
        for (int d = 0; d < 64; ++d) {
            float4 qf = *(const float4*)&Qs[d * PAD + m0];
            float4 kf = *(const float4*)&Ks[d * PAD + n0];
            const float qa[4] = {qf.x, qf.y, qf.z, qf.w};
            const float ka[4] = {kf.x, kf.y, kf.z, kf.w};
#pragma unroll
            for (int i = 0; i < 4; ++i)
#pragma unroll
                for (int j = 0; j < 4; ++j)
                    acc[i][j] += qa[i] * ka[j];
        }

        // Online softmax, row stats reduced across the 16 tx lanes
#pragma unroll
        for (int i = 0; i < 4; ++i) {
            float mx = fmaxf(fmaxf(acc[i][0], acc[i][1]), fmaxf(acc[i][2], acc[i][3]));
#pragma unroll
            for (int ofs = 8; ofs >= 1; ofs >>= 1)
                mx = fmaxf(mx, __shfl_xor_sync(0xffffffffu, mx, ofs));
            const float nm = fmaxf(rm[i], mx);
            float p[4], ls = 0.f;
#pragma unroll
            for (int j = 0; j < 4; ++j) { p[j] = __expf(acc[i][j] - nm); ls += p[j]; }
#pragma unroll
            for (int ofs = 8; ofs >= 1; ofs >>= 1)
                ls += __shfl_xor_sync(0xffffffffu, ls, ofs);
            const float sc = __expf(rm[i] - nm);
            rl[i] = rl[i] * sc + ls;
            rm[i] = nm;
#pragma unroll
            for (int j = 0; j < 4; ++j) o[i][j] *= sc;
#pragma unroll
            for (int j = 0; j < 4; ++j)
                Ps[(n0 + j) * PAD + m0 + i] = p[j];
        }
        __syncthreads();

        // O += P V
#pragma unroll
        for (int j = 0; j < 64; ++j) {
            float4 pf = *(const float4*)&Ps[j * PAD + m0];
            float4 vf = *(const float4*)&Vs[j * PAD + n0];
            const float pa[4] = {pf.x, pf.y, pf.z, pf.w};
            const float va[4] = {vf.x, vf.y, vf.z, vf.w};
#pragma unroll
            for (int i = 0; i < 4; ++i)
#pragma unroll
                for (int jj = 0; jj < 4; ++jj)
                    o[i][jj] += pa[i] * va[jj];
        }
        __syncthreads();
    }

    // Epilogue: normalize, write [b][s][h*64+dk]
#pragma unroll
    for (int i = 0; i < 4; ++i) {
        const float inv = 1.f / rl[i];
        const int s = qb + m0 + i;
        float4 v;
        v.x = o[i][0] * inv; v.y = o[i][1] * inv;
        v.z = o[i][2] * inv; v.w = o[i][3] * inv;
        *(float4*)&g_O[((size_t)(b * SEQ + s) * DMODEL) + h * DK + n0] = v;
    }
}

// ---------------------------------------------------------------------------
// Launch
// ---------------------------------------------------------------------------
extern "C" void kernel_launch(void* const* d_in, const int* in_sizes, int n_in,
                              void* d_out, int out_size)
{
    const float* q  = (const float*)d_in[0];
    const float* k  = (const float*)d_in[1];
    const float* v  = (const float*)d_in[2];
    const float* Wq = (const float*)d_in[3];
    const float* bq = (const float*)d_in[4];
    const float* Wk = (const float*)d_in[5];
    const float* bk = (const float*)d_in[6];
    const float* Wv = (const float*)d_in[7];
    const float* bv = (const float*)d_in[8];
    const float* Wo = (const float*)d_in[9];
    const float* bo = (const float*)d_in[10];
    float* out = (float*)d_out;

    float *pQ, *pK, *pV, *pO;
    cudaGetSymbolAddress((void**)&pQ, g_Q);
    cudaGetSymbolAddress((void**)&pK, g_K);
    cudaGetSymbolAddress((void**)&pV, g_V);
    cudaGetSymbolAddress((void**)&pO, g_O);

    cudaFuncSetAttribute(flash_kernel,
                         cudaFuncAttributeMaxDynamicSharedMemorySize, FLASH_SMEM);

    dim3 ggrid(DMODEL / 128, MROWS / 128);   // (8, 64)
    gemm_kernel<<<ggrid, 256>>>(q, Wq, bq, pQ, 0);
    gemm_kernel<<<ggrid, 256>>>(k, Wk, bk, pK, 0);
    gemm_kernel<<<ggrid, 256>>>(v, Wv, bv, pV, 0);

    dim3 fgrid(SEQ / 64, HEADS, BATCH);      // (32, 16, 4)
    flash_kernel<<<fgrid, 256, FLASH_SMEM>>>();

    gemm_kernel<<<ggrid, 256>>>(pO, Wo, bo, out, 1);
}

// round 7
// speedup vs baseline: 1.3734x; 1.3734x over previous
#include <cuda_runtime.h>
#include <cuda_bf16.h>
#include <cstdint>

// ---------------------------------------------------------------------------
// MultiHeadAttention: B=4, H=16, S=2048, D=1024, dk=64, fp32.
// Dense GEMMs via mma.sync bf16x3 split (HMMA, base-ISA; tcgen05 is rejected
// by this harness's compute_103 virtual target). Flash attention fp32.
// ---------------------------------------------------------------------------

#define BATCH 4
#define HEADS 16
#define SEQ   2048
#define DMODEL 1024
#define DK    64
#define MROWS (BATCH * SEQ)        // 8192

// ---------------- scratch (__device__ globals; no allocation allowed) -------
__device__ float g_Q[BATCH * HEADS * SEQ * DK];   // [b][h][s][dk]
__device__ float g_K[BATCH * HEADS * SEQ * DK];
__device__ float g_V[BATCH * HEADS * SEQ * DK];
__device__ float g_O[BATCH * SEQ * DMODEL];       // [b][s][h*dk]

__device__ __nv_bfloat16 g_Ahi[MROWS * DMODEL];
__device__ __nv_bfloat16 g_Alo[MROWS * DMODEL];
__device__ __nv_bfloat16 g_Whi[DMODEL * DMODEL];
__device__ __nv_bfloat16 g_Wlo[DMODEL * DMODEL];

// ---------------- HMMA helpers (base ISA, sm_80+) ---------------------------
__device__ __forceinline__ uint32_t smem_u32(const void* p) {
    uint32_t a;
    asm("{ .reg .u64 t; cvta.to.shared.u64 t, %1; cvt.u32.u64 %0, t; }" : "=r"(a) : "l"(p));
    return a;
}
__device__ __forceinline__ void ldm_x4(uint32_t* r, uint32_t addr) {
    asm volatile("ldmatrix.sync.aligned.m8n8.x4.shared.b16 {%0,%1,%2,%3}, [%4];"
                 : "=r"(r[0]), "=r"(r[1]), "=r"(r[2]), "=r"(r[3]) : "r"(addr));
}
__device__ __forceinline__ void mma16816(float* c, const uint32_t* a, const uint32_t* b) {
    asm volatile("mma.sync.aligned.m16n8k16.row.col.f32.bf16.bf16.f32 "
                 "{%0,%1,%2,%3}, {%4,%5,%6,%7}, {%8,%9}, {%0,%1,%2,%3};"
                 : "+f"(c[0]), "+f"(c[1]), "+f"(c[2]), "+f"(c[3])
                 : "r"(a[0]), "r"(a[1]), "r"(a[2]), "r"(a[3]), "r"(b[0]), "r"(b[1]));
}

// ---------------------------------------------------------------------------
// Split kernel: fp32 -> (bf16 hi, bf16 lo)
// ---------------------------------------------------------------------------
__global__ void __launch_bounds__(256)
split_kernel(const float* __restrict__ x, __nv_bfloat16* __restrict__ hi,
             __nv_bfloat16* __restrict__ lo, int n)
{
    int i = (blockIdx.x * blockDim.x + threadIdx.x) * 4;
    const int stride = gridDim.x * blockDim.x * 4;
    for (; i < n; i += stride) {
        float4 v = *(const float4*)(x + i);
        __nv_bfloat16 h0 = __float2bfloat16(v.x);
        __nv_bfloat16 h1 = __float2bfloat16(v.y);
        __nv_bfloat16 h2 = __float2bfloat16(v.z);
        __nv_bfloat16 h3 = __float2bfloat16(v.w);
        __nv_bfloat16 l0 = __float2bfloat16(v.x - __bfloat162float(h0));
        __nv_bfloat16 l1 = __float2bfloat16(v.y - __bfloat162float(h1));
        __nv_bfloat16 l2 = __float2bfloat16(v.z - __bfloat162float(h2));
        __nv_bfloat16 l3 = __float2bfloat16(v.w - __bfloat162float(h3));
        *(__nv_bfloat162*)(hi + i)     = __nv_bfloat162(h0, h1);
        *(__nv_bfloat162*)(hi + i + 2) = __nv_bfloat162(h2, h3);
        *(__nv_bfloat162*)(lo + i)     = __nv_bfloat162(l0, l1);
        *(__nv_bfloat162*)(lo + i + 2) = __nv_bfloat162(l2, l3);
    }
}

// ---------------------------------------------------------------------------
// HMMA GEMM: C[M=8192,N=1024] = A[M,K]*B[N,K]^T + bias, bf16x3 split.
// Block 128x128, K-tile 32, 8 warps (2m x 4n), warp tile 64x32.
// Both A and B are K-major => non-transposed ldmatrix for both operands.
// mode 0: scatter into [b][h][s][dk]; mode 1: row-major [M,N].
// ---------------------------------------------------------------------------
#define BM 128
#define BN 128
#define BK 32
#define SROW 40     // padded smem row stride (bf16) -> 80B rows, 16B-aligned

__global__ void __launch_bounds__(256, 1)
gemm_mma(const __nv_bfloat16* __restrict__ Ahi, const __nv_bfloat16* __restrict__ Alo,
         const __nv_bfloat16* __restrict__ Bhi, const __nv_bfloat16* __restrict__ Blo,
         const float* __restrict__ bias, float* __restrict__ C, int mode)
{
    __shared__ __nv_bfloat16 sAhi[BM * SROW];
    __shared__ __nv_bfloat16 sAlo[BM * SROW];
    __shared__ __nv_bfloat16 sBhi[BN * SROW];
    __shared__ __nv_bfloat16 sBlo[BN * SROW];

    const int t = threadIdx.x;
    const int w = t >> 5, lane = t & 31;
    const int bm = blockIdx.y * BM;
    const int bn = blockIdx.x * BN;
    const int wm = (w >> 2) * 64;      // warp m-offset (0/64)
    const int wn = (w & 3) * 32;       // warp n-offset (0/32/64/96)

    float acc[4][4][4];
#pragma unroll
    for (int mi = 0; mi < 4; ++mi)
#pragma unroll
        for (int ni = 0; ni < 4; ++ni)
#pragma unroll
            for (int r = 0; r < 4; ++r) acc[mi][ni][r] = 0.f;

    // per-lane ldmatrix source coordinates
    const int aRow = wm + (lane & 15);
    const int aCol = (lane >> 4) * 8;
    const int bRowN = wn + (lane & 7) + ((lane >> 4) << 3);   // n within warp tile
    const int bColK = ((lane >> 3) & 1) * 8;                  // k sub-offset

    const uint32_t uAhi = smem_u32(sAhi);
    const uint32_t uAlo = smem_u32(sAlo);
    const uint32_t uBhi = smem_u32(sBhi);
    const uint32_t uBlo = smem_u32(sBlo);

    for (int kt = 0; kt < DMODEL / BK; ++kt) {
        const int kbase = kt * BK;

        // ---- fill smem: 4 matrices, each 128x32 bf16 (2 x 16B chunks/thread) ----
#pragma unroll
        for (int it = 0; it < 2; ++it) {
            const int c = t + it * 256;
            const int row = c >> 2;            // 0..127
            const int col = (c & 3) * 8;       // 0,8,16,24
            const size_t gA = (size_t)(bm + row) * DMODEL + kbase + col;
            const size_t gB = (size_t)(bn + row) * DMODEL + kbase + col;
            *(uint4*)&sAhi[row * SROW + col] = *(const uint4*)(Ahi + gA);
            *(uint4*)&sAlo[row * SROW + col] = *(const uint4*)(Alo + gA);
            *(uint4*)&sBhi[row * SROW + col] = *(const uint4*)(Bhi + gB);
            *(uint4*)&sBlo[row * SROW + col] = *(const uint4*)(Blo + gB);
        }
        __syncthreads();

#pragma unroll
        for (int ks = 0; ks < 2; ++ks) {
            const int k0 = ks * 16;

            // B fragments: 2 x ldmatrix.x4, each covering two 16x8 n-tiles
            uint32_t bhi[4][2], blo[4][2];
#pragma unroll
            for (int nb = 0; nb < 2; ++nb) {
                uint32_t r[4];
                const uint32_t off = (uint32_t)((bRowN + nb * 16) * SROW + k0 + bColK) * 2;
                ldm_x4(r, uBhi + off);
                bhi[nb * 2 + 0][0] = r[0]; bhi[nb * 2 + 0][1] = r[1];
                bhi[nb * 2 + 1][0] = r[2]; bhi[nb * 2 + 1][1] = r[3];
                ldm_x4(r, uBlo + off);
                blo[nb * 2 + 0][0] = r[0]; blo[nb * 2 + 0][1] = r[1];
                blo[nb * 2 + 1][0] = r[2]; blo[nb * 2 + 1][1] = r[3];
            }

#pragma unroll
            for (int mi = 0; mi < 4; ++mi) {
                uint32_t ahi[4], alo[4];
                const uint32_t off = (uint32_t)((aRow + mi * 16) * SROW + k0 + aCol) * 2;
                ldm_x4(ahi, uAhi + off);
                ldm_x4(alo, uAlo + off);
#pragma unroll
                for (int ni = 0; ni < 4; ++ni) {
                    mma16816(acc[mi][ni], ahi, bhi[ni]);
                    mma16816(acc[mi][ni], ahi, blo[ni]);
                    mma16816(acc[mi][ni], alo, bhi[ni]);
                }
            }
        }
        __syncthreads();
    }

    // ---- epilogue ----
    const int r0 = lane >> 2;
    const int cp = (lane & 3) * 2;
#pragma unroll
    for (int mi = 0; mi < 4; ++mi) {
#pragma unroll
        for (int ni = 0; ni < 4; ++ni) {
            const int n = bn + wn + ni * 8 + cp;
            const float2 b2 = *(const float2*)(bias + n);
#pragma unroll
            for (int half = 0; half < 2; ++half) {
                const int m = bm + wm + mi * 16 + r0 + half * 8;
                float2 v;
                v.x = acc[mi][ni][half * 2 + 0] + b2.x;
                v.y = acc[mi][ni][half * 2 + 1] + b2.y;
                if (mode == 0) {
                    const int bb = m >> 11, s = m & 2047;
                    const int h = n >> 6, dd = n & 63;
                    *(float2*)(C + (((size_t)(bb * HEADS + h) * SEQ + s) << 6) + dd) = v;
                } else {
                    *(float2*)(C + (size_t)m * DMODEL + n) = v;
                }
            }
        }
    }
}

// ---------------------------------------------------------------------------
// Flash attention (fp32) — unchanged (passing, ~85% of FFMA roofline).
// ---------------------------------------------------------------------------
#define PAD 68
#define FLASH_SMEM (4 * 64 * PAD * 4)

__global__ void __launch_bounds__(256)
flash_kernel()
{
    extern __shared__ float smf[];
    float* Qs = smf;
    float* Ks = Qs + 64 * PAD;
    float* Vs = Ks + 64 * PAD;
    float* Ps = Vs + 64 * PAD;

    const int t  = threadIdx.x;
    const int b  = blockIdx.z;
    const int h  = blockIdx.y;
    const int qb = blockIdx.x * 64;

    const float* Qg = g_Q + ((size_t)(b * HEADS + h) * SEQ) * DK;
    const float* Kg = g_K + ((size_t)(b * HEADS + h) * SEQ) * DK;
    const float* Vg = g_V + ((size_t)(b * HEADS + h) * SEQ) * DK;

    const int lrow = t >> 2;
    const int dbase = (t & 3) << 4;

    {
        const float4* qr = (const float4*)(Qg + (size_t)(qb + lrow) * DK + dbase);
#pragma unroll
        for (int i = 0; i < 4; ++i) {
            float4 v = qr[i];
            const int d = dbase + i * 4;
            Qs[(d + 0) * PAD + lrow] = v.x * 0.125f;
            Qs[(d + 1) * PAD + lrow] = v.y * 0.125f;
            Qs[(d + 2) * PAD + lrow] = v.z * 0.125f;
            Qs[(d + 3) * PAD + lrow] = v.w * 0.125f;
        }
    }

    const int tx = t & 15, ty = t >> 4;
    const int m0 = ty * 4, n0 = tx * 4;

    float rm[4], rl[4], o[4][4];
#pragma unroll
    for (int i = 0; i < 4; ++i) {
        rm[i] = -1e30f; rl[i] = 0.f;
#pragma unroll
        for (int j = 0; j < 4; ++j) o[i][j] = 0.f;
    }

    for (int kv = 0; kv < SEQ / 64; ++kv) {
        const int kb = kv * 64;
        {
            const float4* kr = (const float4*)(Kg + (size_t)(kb + lrow) * DK + dbase);
            const float4* vr = (const float4*)(Vg + (size_t)(kb + lrow) * DK + dbase);
#pragma unroll
            for (int i = 0; i < 4; ++i) {
                float4 v = kr[i];
                const int d = dbase + i * 4;
                Ks[(d + 0) * PAD + lrow] = v.x;
                Ks[(d + 1) * PAD + lrow] = v.y;
                Ks[(d + 2) * PAD + lrow] = v.z;
                Ks[(d + 3) * PAD + lrow] = v.w;
                *(float4*)&Vs[lrow * PAD + dbase + i * 4] = vr[i];
            }
        }
        __syncthreads();

        float acc[4][4];
#pragma unroll
        for (int i = 0; i < 4; ++i)
#pragma unroll
            for (int j = 0; j < 4; ++j) acc[i][j] = 0.f;

#pragma unroll
        for (int d = 0; d < 64; ++d) {
            float4 qf = *(const float4*)&Qs[d * PAD + m0];
            float4 kf = *(const float4*)&Ks[d * PAD + n0];
            const float qa[4] = {qf.x, qf.y, qf.z, qf.w};
            const float ka[4] = {kf.x, kf.y, kf.z, kf.w};
#pragma unroll
            for (int i = 0; i < 4; ++i)
#pragma unroll
                for (int j = 0; j < 4; ++j)
                    acc[i][j] += qa[i] * ka[j];
        }

#pragma unroll
        for (int i = 0; i < 4; ++i) {
            float mx = fmaxf(fmaxf(acc[i][0], acc[i][1]), fmaxf(acc[i][2], acc[i][3]));
#pragma unroll
            for (int ofs = 8; ofs >= 1; ofs >>= 1)
                mx = fmaxf(mx, __shfl_xor_sync(0xffffffffu, mx, ofs));
            const float nm = fmaxf(rm[i], mx);
            float p[4], ls = 0.f;
#pragma unroll
            for (int j = 0; j < 4; ++j) { p[j] = __expf(acc[i][j] - nm); ls += p[j]; }
#pragma unroll
            for (int ofs = 8; ofs >= 1; ofs >>= 1)
                ls += __shfl_xor_sync(0xffffffffu, ls, ofs);
            const float sc = __expf(rm[i] - nm);
            rl[i] = rl[i] * sc + ls;
            rm[i] = nm;
#pragma unroll
            for (int j = 0; j < 4; ++j) o[i][j] *= sc;
#pragma unroll
            for (int j = 0; j < 4; ++j)
                Ps[(n0 + j) * PAD + m0 + i] = p[j];
        }
        __syncthreads();

#pragma unroll
        for (int j = 0; j < 64; ++j) {
            float4 pf = *(const float4*)&Ps[j * PAD + m0];
            float4 vf = *(const float4*)&Vs[j * PAD + n0];
            const float pa[4] = {pf.x, pf.y, pf.z, pf.w};
            const float va[4] = {vf.x, vf.y, vf.z, vf.w};
#pragma unroll
            for (int i = 0; i < 4; ++i)
#pragma unroll
                for (int jj = 0; jj < 4; ++jj)
                    o[i][jj] += pa[i] * va[jj];
        }
        __syncthreads();
    }

#pragma unroll
    for (int i = 0; i < 4; ++i) {
        const float inv = 1.f / rl[i];
        const int s = qb + m0 + i;
        float4 v;
        v.x = o[i][0] * inv; v.y = o[i][1] * inv;
        v.z = o[i][2] * inv; v.w = o[i][3] * inv;
        *(float4*)&g_O[((size_t)(b * SEQ + s) * DMODEL) + h * DK + n0] = v;
    }
}

// ---------------------------------------------------------------------------
// Launch
// ---------------------------------------------------------------------------
extern "C" void kernel_launch(void* const* d_in, const int* in_sizes, int n_in,
                              void* d_out, int out_size)
{
    const float* q  = (const float*)d_in[0];
    const float* k  = (const float*)d_in[1];
    const float* v  = (const float*)d_in[2];
    const float* Wq = (const float*)d_in[3];
    const float* bq = (const float*)d_in[4];
    const float* Wk = (const float*)d_in[5];
    const float* bk = (const float*)d_in[6];
    const float* Wv = (const float*)d_in[7];
    const float* bv = (const float*)d_in[8];
    const float* Wo = (const float*)d_in[9];
    const float* bo = (const float*)d_in[10];
    float* out = (float*)d_out;

    float *pQ, *pK, *pV, *pO;
    cudaGetSymbolAddress((void**)&pQ, g_Q);
    cudaGetSymbolAddress((void**)&pK, g_K);
    cudaGetSymbolAddress((void**)&pV, g_V);
    cudaGetSymbolAddress((void**)&pO, g_O);
    __nv_bfloat16 *pAhi, *pAlo, *pWhi, *pWlo;
    cudaGetSymbolAddress((void**)&pAhi, g_Ahi);
    cudaGetSymbolAddress((void**)&pAlo, g_Alo);
    cudaGetSymbolAddress((void**)&pWhi, g_Whi);
    cudaGetSymbolAddress((void**)&pWlo, g_Wlo);

    cudaFuncSetAttribute(flash_kernel, cudaFuncAttributeMaxDynamicSharedMemorySize, FLASH_SMEM);

    const dim3 ggrid(DMODEL / BN, MROWS / BM);   // (8, 64)

    auto do_gemm = [&](const float* act, const float* W, const float* bias,
                       float* dst, int mode) {
        split_kernel<<<1024, 256>>>(act, pAhi, pAlo, MROWS * DMODEL);
        split_kernel<<<256, 256>>>(W, pWhi, pWlo, DMODEL * DMODEL);
        gemm_mma<<<ggrid, 256>>>(pAhi, pAlo, pWhi, pWlo, bias, dst, mode);
    };

    do_gemm(q, Wq, bq, pQ, 0);
    do_gemm(k, Wk, bk, pK, 0);
    do_gemm(v, Wv, bv, pV, 0);

    const dim3 fgrid(SEQ / 64, HEADS, BATCH);    // (32, 16, 4)
    flash_kernel<<<fgrid, 256, FLASH_SMEM>>>();

    do_gemm(pO, Wo, bo, out, 1);
}

// round 11
// speedup vs baseline: 2.1736x; 1.5827x over previous
#include <cuda_runtime.h>
#include <cuda_bf16.h>
#include <cstdint>

// ---------------------------------------------------------------------------
// MultiHeadAttention: B=4, H=16, S=2048, D=1024, dk=64, fp32.
// Everything on HMMA (mma.sync bf16x3 split; tcgen05 rejected by the
// harness's compute_103 virtual target):
//   QKV proj GEMMs -> bf16 hi/lo Q,K,V directly (scale folded into Q)
//   flash attention: QK^T and P.V as bf16x3 HMMA with online softmax
//   out proj GEMM -> fp32
// ---------------------------------------------------------------------------

#define BATCH 4
#define HEADS 16
#define SEQ   2048
#define DMODEL 1024
#define DK    64
#define MROWS (BATCH * SEQ)        // 8192

// ---------------- scratch (__device__ globals; no allocation allowed) -------
__device__ __nv_bfloat16 g_Qhi[BATCH * HEADS * SEQ * DK];  // [b][h][s][dk]
__device__ __nv_bfloat16 g_Qlo[BATCH * HEADS * SEQ * DK];
__device__ __nv_bfloat16 g_Khi[BATCH * HEADS * SEQ * DK];
__device__ __nv_bfloat16 g_Klo[BATCH * HEADS * SEQ * DK];
__device__ __nv_bfloat16 g_Vhi[BATCH * HEADS * SEQ * DK];
__device__ __nv_bfloat16 g_Vlo[BATCH * HEADS * SEQ * DK];
__device__ float g_O[BATCH * SEQ * DMODEL];                // [b][s][h*dk]

__device__ __nv_bfloat16 g_Ahi[MROWS * DMODEL];
__device__ __nv_bfloat16 g_Alo[MROWS * DMODEL];
__device__ __nv_bfloat16 g_Whi[DMODEL * DMODEL];
__device__ __nv_bfloat16 g_Wlo[DMODEL * DMODEL];

// ---------------- HMMA helpers (base ISA, sm_80+) ---------------------------
__device__ __forceinline__ uint32_t smem_u32(const void* p) {
    uint32_t a;
    asm("{ .reg .u64 t; cvta.to.shared.u64 t, %1; cvt.u32.u64 %0, t; }" : "=r"(a) : "l"(p));
    return a;
}
__device__ __forceinline__ void ldm_x4(uint32_t* r, uint32_t addr) {
    asm volatile("ldmatrix.sync.aligned.m8n8.x4.shared.b16 {%0,%1,%2,%3}, [%4];"
                 : "=r"(r[0]), "=r"(r[1]), "=r"(r[2]), "=r"(r[3]) : "r"(addr));
}
__device__ __forceinline__ void mma16816(float* c, const uint32_t* a, const uint32_t* b) {
    asm volatile("mma.sync.aligned.m16n8k16.row.col.f32.bf16.bf16.f32 "
                 "{%0,%1,%2,%3}, {%4,%5,%6,%7}, {%8,%9}, {%0,%1,%2,%3};"
                 : "+f"(c[0]), "+f"(c[1]), "+f"(c[2]), "+f"(c[3])
                 : "r"(a[0]), "r"(a[1]), "r"(a[2]), "r"(a[3]), "r"(b[0]), "r"(b[1]));
}
__device__ __forceinline__ uint32_t packbf(float a, float b) {
    __nv_bfloat162 r = __floats2bfloat162_rn(a, b);
    return *(uint32_t*)&r;
}

// ---------------------------------------------------------------------------
// Split kernel: fp32 -> (bf16 hi, bf16 lo)
// ---------------------------------------------------------------------------
__global__ void __launch_bounds__(256)
split_kernel(const float* __restrict__ x, __nv_bfloat16* __restrict__ hi,
             __nv_bfloat16* __restrict__ lo, int n)
{
    int i = (blockIdx.x * blockDim.x + threadIdx.x) * 4;
    const int stride = gridDim.x * blockDim.x * 4;
    for (; i < n; i += stride) {
        float4 v = *(const float4*)(x + i);
        __nv_bfloat16 h0 = __float2bfloat16(v.x);
        __nv_bfloat16 h1 = __float2bfloat16(v.y);
        __nv_bfloat16 h2 = __float2bfloat16(v.z);
        __nv_bfloat16 h3 = __float2bfloat16(v.w);
        __nv_bfloat16 l0 = __float2bfloat16(v.x - __bfloat162float(h0));
        __nv_bfloat16 l1 = __float2bfloat16(v.y - __bfloat162float(h1));
        __nv_bfloat16 l2 = __float2bfloat16(v.z - __bfloat162float(h2));
        __nv_bfloat16 l3 = __float2bfloat16(v.w - __bfloat162float(h3));
        *(__nv_bfloat162*)(hi + i)     = __nv_bfloat162(h0, h1);
        *(__nv_bfloat162*)(hi + i + 2) = __nv_bfloat162(h2, h3);
        *(__nv_bfloat162*)(lo + i)     = __nv_bfloat162(l0, l1);
        *(__nv_bfloat162*)(lo + i + 2) = __nv_bfloat162(l2, l3);
    }
}

// ---------------------------------------------------------------------------
// HMMA GEMM: C[M=8192,N=1024] = A[M,K]*B[N,K]^T + bias, bf16x3 split.
// Block 128x128, K-tile 32, 8 warps (2m x 4n), warp tile 64x32.
// mode 0: v=(acc+bias)*scale, split hi/lo bf16, scatter [b][h][s][dk]
// mode 1: fp32 row-major [M,N]
// ---------------------------------------------------------------------------
#define BM 128
#define BN 128
#define BK 32
#define SROW 40

__global__ void __launch_bounds__(256, 1)
gemm_mma(const __nv_bfloat16* __restrict__ Ahi, const __nv_bfloat16* __restrict__ Alo,
         const __nv_bfloat16* __restrict__ Bhi, const __nv_bfloat16* __restrict__ Blo,
         const float* __restrict__ bias, float* __restrict__ C,
         __nv_bfloat16* __restrict__ Chi, __nv_bfloat16* __restrict__ Clo,
         float scale, int mode)
{
    __shared__ __nv_bfloat16 sAhi[BM * SROW];
    __shared__ __nv_bfloat16 sAlo[BM * SROW];
    __shared__ __nv_bfloat16 sBhi[BN * SROW];
    __shared__ __nv_bfloat16 sBlo[BN * SROW];

    const int t = threadIdx.x;
    const int w = t >> 5, lane = t & 31;
    const int bm = blockIdx.y * BM;
    const int bn = blockIdx.x * BN;
    const int wm = (w >> 2) * 64;
    const int wn = (w & 3) * 32;

    float acc[4][4][4];
#pragma unroll
    for (int mi = 0; mi < 4; ++mi)
#pragma unroll
        for (int ni = 0; ni < 4; ++ni)
#pragma unroll
            for (int r = 0; r < 4; ++r) acc[mi][ni][r] = 0.f;

    const int aRow = wm + (lane & 15);
    const int aCol = (lane >> 4) * 8;
    const int bRowN = wn + (lane & 7) + ((lane >> 4) << 3);
    const int bColK = ((lane >> 3) & 1) * 8;

    const uint32_t uAhi = smem_u32(sAhi);
    const uint32_t uAlo = smem_u32(sAlo);
    const uint32_t uBhi = smem_u32(sBhi);
    const uint32_t uBlo = smem_u32(sBlo);

    for (int kt = 0; kt < DMODEL / BK; ++kt) {
        const int kbase = kt * BK;

#pragma unroll
        for (int it = 0; it < 2; ++it) {
            const int c = t + it * 256;
            const int row = c >> 2;
            const int col = (c & 3) * 8;
            const size_t gA = (size_t)(bm + row) * DMODEL + kbase + col;
            const size_t gB = (size_t)(bn + row) * DMODEL + kbase + col;
            *(uint4*)&sAhi[row * SROW + col] = *(const uint4*)(Ahi + gA);
            *(uint4*)&sAlo[row * SROW + col] = *(const uint4*)(Alo + gA);
            *(uint4*)&sBhi[row * SROW + col] = *(const uint4*)(Bhi + gB);
            *(uint4*)&sBlo[row * SROW + col] = *(const uint4*)(Blo + gB);
        }
        __syncthreads();

#pragma unroll
        for (int ks = 0; ks < 2; ++ks) {
            const int k0 = ks * 16;
            uint32_t bhi[4][2], blo[4][2];
#pragma unroll
            for (int nb = 0; nb < 2; ++nb) {
                uint32_t r[4];
                const uint32_t off = (uint32_t)((bRowN + nb * 16) * SROW + k0 + bColK) * 2;
                ldm_x4(r, uBhi + off);
                bhi[nb * 2 + 0][0] = r[0]; bhi[nb * 2 + 0][1] = r[1];
                bhi[nb * 2 + 1][0] = r[2]; bhi[nb * 2 + 1][1] = r[3];
                ldm_x4(r, uBlo + off);
                blo[nb * 2 + 0][0] = r[0]; blo[nb * 2 + 0][1] = r[1];
                blo[nb * 2 + 1][0] = r[2]; blo[nb * 2 + 1][1] = r[3];
            }
#pragma unroll
            for (int mi = 0; mi < 4; ++mi) {
                uint32_t ahi[4], alo[4];
                const uint32_t off = (uint32_t)((aRow + mi * 16) * SROW + k0 + aCol) * 2;
                ldm_x4(ahi, uAhi + off);
                ldm_x4(alo, uAlo + off);
#pragma unroll
                for (int ni = 0; ni < 4; ++ni) {
                    mma16816(acc[mi][ni], ahi, bhi[ni]);
                    mma16816(acc[mi][ni], ahi, blo[ni]);
                    mma16816(acc[mi][ni], alo, bhi[ni]);
                }
            }
        }
        __syncthreads();
    }

    // ---- epilogue ----
    const int r0 = lane >> 2;
    const int cp = (lane & 3) * 2;
#pragma unroll
    for (int mi = 0; mi < 4; ++mi) {
#pragma unroll
        for (int ni = 0; ni < 4; ++ni) {
            const int n = bn + wn + ni * 8 + cp;
            const float2 b2 = *(const float2*)(bias + n);
#pragma unroll
            for (int half = 0; half < 2; ++half) {
                const int m = bm + wm + mi * 16 + r0 + half * 8;
                float vx = (acc[mi][ni][half * 2 + 0] + b2.x) * scale;
                float vy = (acc[mi][ni][half * 2 + 1] + b2.y) * scale;
                if (mode == 0) {
                    const int bb = m >> 11, s = m & 2047;
                    const int h = n >> 6, dd = n & 63;
                    const size_t off = (((size_t)(bb * HEADS + h) * SEQ + s) << 6) + dd;
                    __nv_bfloat16 hx = __float2bfloat16(vx);
                    __nv_bfloat16 hy = __float2bfloat16(vy);
                    *(uint32_t*)(Chi + off) = packbf(vx, vy);
                    *(uint32_t*)(Clo + off) = packbf(vx - __bfloat162float(hx),
                                                     vy - __bfloat162float(hy));
                } else {
                    float2 v; v.x = vx; v.y = vy;
                    *(float2*)(C + (size_t)m * DMODEL + n) = v;
                }
            }
        }
    }
}

// ---------------------------------------------------------------------------
// Flash attention via HMMA bf16x3.
// Block = 128 threads (4 warps), q-tile 64 (warp w owns rows w*16..w*16+15),
// kv-tile 64. S-fragment of QK^T reused directly as A-fragment of P.V.
// ---------------------------------------------------------------------------
#define KS 72                                   // smem row stride (bf16)
#define FLASH_SMEM (6 * 64 * KS * 2)            // 55296 B dynamic

__global__ void __launch_bounds__(128)
flash_mma()
{
    extern __shared__ __nv_bfloat16 fsm[];
    __nv_bfloat16* sQh = fsm;
    __nv_bfloat16* sQl = sQh + 64 * KS;
    __nv_bfloat16* sKh = sQl + 64 * KS;
    __nv_bfloat16* sKl = sKh + 64 * KS;
    __nv_bfloat16* sVh = sKl + 64 * KS;         // transposed: [d][kv]
    __nv_bfloat16* sVl = sVh + 64 * KS;

    const int t = threadIdx.x, w = t >> 5, lane = t & 31;
    const int b = blockIdx.z, h = blockIdx.y, qb = blockIdx.x * 64;
    const size_t hb = (size_t)(b * HEADS + h) * SEQ * DK;

    const __nv_bfloat16* Qh = g_Qhi + hb + (size_t)qb * DK;
    const __nv_bfloat16* Ql = g_Qlo + hb + (size_t)qb * DK;
    const __nv_bfloat16* Khg = g_Khi + hb;
    const __nv_bfloat16* Klg = g_Klo + hb;
    const __nv_bfloat16* Vhg = g_Vhi + hb;
    const __nv_bfloat16* Vlg = g_Vlo + hb;

    // ---- load Q tile (64x64 hi/lo) ----
#pragma unroll
    for (int it = 0; it < 4; ++it) {
        const int c = t + it * 128;
        const int row = c >> 3, col = (c & 7) * 8;
        *(uint4*)&sQh[row * KS + col] = *(const uint4*)(Qh + row * DK + col);
        *(uint4*)&sQl[row * KS + col] = *(const uint4*)(Ql + row * DK + col);
    }
    __syncthreads();

    // ---- Q A-fragments (persistent registers) ----
    uint32_t qh[4][4], ql[4][4];
    const int aRow = w * 16 + (lane & 15);
    const int aCol = (lane >> 4) * 8;
    const uint32_t uQh = smem_u32(sQh), uQl = smem_u32(sQl);
#pragma unroll
    for (int ks = 0; ks < 4; ++ks) {
        const uint32_t off = (uint32_t)(aRow * KS + ks * 16 + aCol) * 2;
        ldm_x4(qh[ks], uQh + off);
        ldm_x4(ql[ks], uQl + off);
    }
    __syncthreads();

    float o[8][4];
#pragma unroll
    for (int nt = 0; nt < 8; ++nt)
#pragma unroll
        for (int r = 0; r < 4; ++r) o[nt][r] = 0.f;
    float rm0 = -1e30f, rm1 = -1e30f, rl0 = 0.f, rl1 = 0.f;

    const int bRow = (lane & 7) + ((lane >> 4) << 3);
    const int bCol = ((lane >> 3) & 1) * 8;
    const uint32_t uKh = smem_u32(sKh), uKl = smem_u32(sKl);
    const uint32_t uVh = smem_u32(sVh), uVl = smem_u32(sVl);

    for (int kv = 0; kv < SEQ / 64; ++kv) {
        const __nv_bfloat16* kh = Khg + (size_t)kv * 64 * DK;
        const __nv_bfloat16* kl = Klg + (size_t)kv * 64 * DK;
        const __nv_bfloat16* vh = Vhg + (size_t)kv * 64 * DK;
        const __nv_bfloat16* vl = Vlg + (size_t)kv * 64 * DK;

        // ---- load K (natural) and V (transposed) ----
#pragma unroll
        for (int it = 0; it < 4; ++it) {
            const int c = t + it * 128;
            const int row = c >> 3, col = (c & 7) * 8;
            *(uint4*)&sKh[row * KS + col] = *(const uint4*)(kh + row * DK + col);
            *(uint4*)&sKl[row * KS + col] = *(const uint4*)(kl + row * DK + col);
            union { uint4 u; __nv_bfloat16 e[8]; } th, tl;
            th.u = *(const uint4*)(vh + row * DK + col);
            tl.u = *(const uint4*)(vl + row * DK + col);
#pragma unroll
            for (int e = 0; e < 8; ++e) {
                sVh[(col + e) * KS + row] = th.e[e];
                sVl[(col + e) * KS + row] = tl.e[e];
            }
        }
        __syncthreads();

        // ---- S = Q K^T (bf16x3) ----
        float s[8][4];
#pragma unroll
        for (int nt = 0; nt < 8; ++nt)
#pragma unroll
            for (int r = 0; r < 4; ++r) s[nt][r] = 0.f;

#pragma unroll
        for (int nb = 0; nb < 4; ++nb) {
#pragma unroll
            for (int ks = 0; ks < 4; ++ks) {
                const uint32_t off = (uint32_t)((nb * 16 + bRow) * KS + ks * 16 + bCol) * 2;
                uint32_t kbh[4], kbl[4];
                ldm_x4(kbh, uKh + off);
                ldm_x4(kbl, uKl + off);
                mma16816(s[nb * 2],     qh[ks], kbh);
                mma16816(s[nb * 2],     qh[ks], kbl);
                mma16816(s[nb * 2],     ql[ks], kbh);
                mma16816(s[nb * 2 + 1], qh[ks], kbh + 2);
                mma16816(s[nb * 2 + 1], qh[ks], kbl + 2);
                mma16816(s[nb * 2 + 1], ql[ks], kbh + 2);
            }
        }

        // ---- online softmax (rows l/4 and l/4+8; stats across 4 lanes) ----
        float mx0 = -1e30f, mx1 = -1e30f;
#pragma unroll
        for (int nt = 0; nt < 8; ++nt) {
            mx0 = fmaxf(mx0, fmaxf(s[nt][0], s[nt][1]));
            mx1 = fmaxf(mx1, fmaxf(s[nt][2], s[nt][3]));
        }
        mx0 = fmaxf(mx0, __shfl_xor_sync(0xffffffffu, mx0, 1));
        mx0 = fmaxf(mx0, __shfl_xor_sync(0xffffffffu, mx0, 2));
        mx1 = fmaxf(mx1, __shfl_xor_sync(0xffffffffu, mx1, 1));
        mx1 = fmaxf(mx1, __shfl_xor_sync(0xffffffffu, mx1, 2));
        const float nm0 = fmaxf(rm0, mx0), nm1 = fmaxf(rm1, mx1);
        const float sc0 = __expf(rm0 - nm0), sc1 = __expf(rm1 - nm1);
        rm0 = nm0; rm1 = nm1;

        float ls0 = 0.f, ls1 = 0.f;
#pragma unroll
        for (int nt = 0; nt < 8; ++nt) {
            s[nt][0] = __expf(s[nt][0] - nm0);
            s[nt][1] = __expf(s[nt][1] - nm0);
            s[nt][2] = __expf(s[nt][2] - nm1);
            s[nt][3] = __expf(s[nt][3] - nm1);
            ls0 += s[nt][0] + s[nt][1];
            ls1 += s[nt][2] + s[nt][3];
        }
        ls0 += __shfl_xor_sync(0xffffffffu, ls0, 1);
        ls0 += __shfl_xor_sync(0xffffffffu, ls0, 2);
        ls1 += __shfl_xor_sync(0xffffffffu, ls1, 1);
        ls1 += __shfl_xor_sync(0xffffffffu, ls1, 2);
        rl0 = rl0 * sc0 + ls0;
        rl1 = rl1 * sc1 + ls1;

#pragma unroll
        for (int nt = 0; nt < 8; ++nt) {
            o[nt][0] *= sc0; o[nt][1] *= sc0;
            o[nt][2] *= sc1; o[nt][3] *= sc1;
        }

        // ---- pack P hi/lo fragments (S c-frag == P a-frag layout) ----
        uint32_t ph[4][4], pl[4][4];
#pragma unroll
        for (int j = 0; j < 4; ++j) {
            const float* p0 = s[2 * j];
            const float* p1 = s[2 * j + 1];
            ph[j][0] = packbf(p0[0], p0[1]);
            ph[j][1] = packbf(p0[2], p0[3]);
            ph[j][2] = packbf(p1[0], p1[1]);
            ph[j][3] = packbf(p1[2], p1[3]);
            float r00 = p0[0] - __bfloat162float(__float2bfloat16(p0[0]));
            float r01 = p0[1] - __bfloat162float(__float2bfloat16(p0[1]));
            float r02 = p0[2] - __bfloat162float(__float2bfloat16(p0[2]));
            float r03 = p0[3] - __bfloat162float(__float2bfloat16(p0[3]));
            float r10 = p1[0] - __bfloat162float(__float2bfloat16(p1[0]));
            float r11 = p1[1] - __bfloat162float(__float2bfloat16(p1[1]));
            float r12 = p1[2] - __bfloat162float(__float2bfloat16(p1[2]));
            float r13 = p1[3] - __bfloat162float(__float2bfloat16(p1[3]));
            pl[j][0] = packbf(r00, r01);
            pl[j][1] = packbf(r02, r03);
            pl[j][2] = packbf(r10, r11);
            pl[j][3] = packbf(r12, r13);
        }

        // ---- O += P V (bf16x3) ----
#pragma unroll
        for (int nb = 0; nb < 4; ++nb) {
#pragma unroll
            for (int ks = 0; ks < 4; ++ks) {
                const uint32_t off = (uint32_t)((nb * 16 + bRow) * KS + ks * 16 + bCol) * 2;
                uint32_t vbh[4], vbl[4];
                ldm_x4(vbh, uVh + off);
                ldm_x4(vbl, uVl + off);
                mma16816(o[nb * 2],     ph[ks], vbh);
                mma16816(o[nb * 2],     ph[ks], vbl);
                mma16816(o[nb * 2],     pl[ks], vbh);
                mma16816(o[nb * 2 + 1], ph[ks], vbh + 2);
                mma16816(o[nb * 2 + 1], ph[ks], vbl + 2);
                mma16816(o[nb * 2 + 1], pl[ks], vbh + 2);
            }
        }
        __syncthreads();
    }

    // ---- epilogue: normalize and write [b][s][h*64+d] fp32 ----
    const float inv0 = 1.f / rl0, inv1 = 1.f / rl1;
    const int row0 = qb + w * 16 + (lane >> 2);
    const int cbase = h * DK + 2 * (lane & 3);
    float* ob = g_O + ((size_t)b * SEQ + row0) * DMODEL;
#pragma unroll
    for (int nt = 0; nt < 8; ++nt) {
        float2 v0; v0.x = o[nt][0] * inv0; v0.y = o[nt][1] * inv0;
        float2 v1; v1.x = o[nt][2] * inv1; v1.y = o[nt][3] * inv1;
        *(float2*)(ob + cbase + nt * 8) = v0;
        *(float2*)(ob + 8 * DMODEL + cbase + nt * 8) = v1;
    }
}

// ---------------------------------------------------------------------------
// Launch
// ---------------------------------------------------------------------------
extern "C" void kernel_launch(void* const* d_in, const int* in_sizes, int n_in,
                              void* d_out, int out_size)
{
    const float* q  = (const float*)d_in[0];
    const float* k  = (const float*)d_in[1];
    const float* v  = (const float*)d_in[2];
    const float* Wq = (const float*)d_in[3];
    const float* bq = (const float*)d_in[4];
    const float* Wk = (const float*)d_in[5];
    const float* bk = (const float*)d_in[6];
    const float* Wv = (const float*)d_in[7];
    const float* bv = (const float*)d_in[8];
    const float* Wo = (const float*)d_in[9];
    const float* bo = (const float*)d_in[10];
    float* out = (float*)d_out;

    float* pO;
    cudaGetSymbolAddress((void**)&pO, g_O);
    __nv_bfloat16 *pAhi, *pAlo, *pWhi, *pWlo;
    __nv_bfloat16 *pQh, *pQl, *pKh, *pKl, *pVh, *pVl;
    cudaGetSymbolAddress((void**)&pAhi, g_Ahi);
    cudaGetSymbolAddress((void**)&pAlo, g_Alo);
    cudaGetSymbolAddress((void**)&pWhi, g_Whi);
    cudaGetSymbolAddress((void**)&pWlo, g_Wlo);
    cudaGetSymbolAddress((void**)&pQh, g_Qhi);
    cudaGetSymbolAddress((void**)&pQl, g_Qlo);
    cudaGetSymbolAddress((void**)&pKh, g_Khi);
    cudaGetSymbolAddress((void**)&pKl, g_Klo);
    cudaGetSymbolAddress((void**)&pVh, g_Vhi);
    cudaGetSymbolAddress((void**)&pVl, g_Vlo);

    cudaFuncSetAttribute(flash_mma, cudaFuncAttributeMaxDynamicSharedMemorySize, FLASH_SMEM);

    const dim3 ggrid(DMODEL / BN, MROWS / BM);   // (8, 64)

    // QKV projections -> bf16 hi/lo, scale folded into Q
    auto proj = [&](const float* act, const float* W, const float* bias,
                    __nv_bfloat16* hi, __nv_bfloat16* lo, float scale) {
        split_kernel<<<1024, 256>>>(act, pAhi, pAlo, MROWS * DMODEL);
        split_kernel<<<256, 256>>>(W, pWhi, pWlo, DMODEL * DMODEL);
        gemm_mma<<<ggrid, 256>>>(pAhi, pAlo, pWhi, pWlo, bias,
                                 nullptr, hi, lo, scale, 0);
    };

    proj(q, Wq, bq, pQh, pQl, 0.125f);
    proj(k, Wk, bk, pKh, pKl, 1.0f);
    proj(v, Wv, bv, pVh, pVl, 1.0f);

    const dim3 fgrid(SEQ / 64, HEADS, BATCH);    // (32, 16, 4)
    flash_mma<<<fgrid, 128, FLASH_SMEM>>>();

    // output projection (fp32 result)
    split_kernel<<<1024, 256>>>(pO, pAhi, pAlo, MROWS * DMODEL);
    split_kernel<<<256, 256>>>(Wo, pWhi, pWlo, DMODEL * DMODEL);
    gemm_mma<<<ggrid, 256>>>(pAhi, pAlo, pWhi, pWlo, bo,
                             out, nullptr, nullptr, 1.0f, 1);
}

// round 12
// speedup vs baseline: 3.0771x; 1.4157x over previous
#include <cuda_runtime.h>
#include <cuda_bf16.h>
#include <cstdint>

// ---------------------------------------------------------------------------
// MultiHeadAttention: B=4, H=16, S=2048, D=1024, dk=64, fp32.
// All matmul on HMMA bf16x3 split (base ISA; tcgen05 rejected by compute_103).
// R12: cp.async double-buffered pipelines (GEMM + flash), ldmatrix.trans for V
// (no scalar transpose), flash epilogue emits O hi/lo directly (no O split).
// ---------------------------------------------------------------------------

#define BATCH 4
#define HEADS 16
#define SEQ   2048
#define DMODEL 1024
#define DK    64
#define MROWS (BATCH * SEQ)        // 8192

// ---------------- scratch (__device__ globals; no allocation allowed) -------
__device__ __nv_bfloat16 g_Qhi[BATCH * HEADS * SEQ * DK];  // [b][h][s][dk]
__device__ __nv_bfloat16 g_Qlo[BATCH * HEADS * SEQ * DK];
__device__ __nv_bfloat16 g_Khi[BATCH * HEADS * SEQ * DK];
__device__ __nv_bfloat16 g_Klo[BATCH * HEADS * SEQ * DK];
__device__ __nv_bfloat16 g_Vhi[BATCH * HEADS * SEQ * DK];
__device__ __nv_bfloat16 g_Vlo[BATCH * HEADS * SEQ * DK];

__device__ __nv_bfloat16 g_Ahi[MROWS * DMODEL];   // also receives O hi from flash
__device__ __nv_bfloat16 g_Alo[MROWS * DMODEL];   // also receives O lo from flash
__device__ __nv_bfloat16 g_Whi[DMODEL * DMODEL];
__device__ __nv_bfloat16 g_Wlo[DMODEL * DMODEL];

// ---------------- helpers (base ISA) ----------------------------------------
__device__ __forceinline__ uint32_t smem_u32(const void* p) {
    uint32_t a;
    asm("{ .reg .u64 t; cvta.to.shared.u64 t, %1; cvt.u32.u64 %0, t; }" : "=r"(a) : "l"(p));
    return a;
}
__device__ __forceinline__ void ldm_x4(uint32_t* r, uint32_t addr) {
    asm volatile("ldmatrix.sync.aligned.m8n8.x4.shared.b16 {%0,%1,%2,%3}, [%4];"
                 : "=r"(r[0]), "=r"(r[1]), "=r"(r[2]), "=r"(r[3]) : "r"(addr));
}
__device__ __forceinline__ void ldm_x4t(uint32_t* r, uint32_t addr) {
    asm volatile("ldmatrix.sync.aligned.m8n8.x4.trans.shared.b16 {%0,%1,%2,%3}, [%4];"
                 : "=r"(r[0]), "=r"(r[1]), "=r"(r[2]), "=r"(r[3]) : "r"(addr));
}
__device__ __forceinline__ void mma16816(float* c, const uint32_t* a, const uint32_t* b) {
    asm volatile("mma.sync.aligned.m16n8k16.row.col.f32.bf16.bf16.f32 "
                 "{%0,%1,%2,%3}, {%4,%5,%6,%7}, {%8,%9}, {%0,%1,%2,%3};"
                 : "+f"(c[0]), "+f"(c[1]), "+f"(c[2]), "+f"(c[3])
                 : "r"(a[0]), "r"(a[1]), "r"(a[2]), "r"(a[3]), "r"(b[0]), "r"(b[1]));
}
__device__ __forceinline__ uint32_t packbf(float a, float b) {
    __nv_bfloat162 r = __floats2bfloat162_rn(a, b);
    return *(uint32_t*)&r;
}
__device__ __forceinline__ void cp16(uint32_t saddr, const void* g) {
    asm volatile("cp.async.cg.shared.global [%0], [%1], 16;" :: "r"(saddr), "l"(g));
}
#define CP_COMMIT() asm volatile("cp.async.commit_group;")
#define CP_WAIT1()  asm volatile("cp.async.wait_group 1;")
#define CP_WAIT0()  asm volatile("cp.async.wait_group 0;")

// ---------------------------------------------------------------------------
// Split kernel: fp32 -> (bf16 hi, bf16 lo)
// ---------------------------------------------------------------------------
__global__ void __launch_bounds__(256)
split_kernel(const float* __restrict__ x, __nv_bfloat16* __restrict__ hi,
             __nv_bfloat16* __restrict__ lo, int n)
{
    int i = (blockIdx.x * blockDim.x + threadIdx.x) * 4;
    const int stride = gridDim.x * blockDim.x * 4;
    for (; i < n; i += stride) {
        float4 v = *(const float4*)(x + i);
        __nv_bfloat16 h0 = __float2bfloat16(v.x);
        __nv_bfloat16 h1 = __float2bfloat16(v.y);
        __nv_bfloat16 h2 = __float2bfloat16(v.z);
        __nv_bfloat16 h3 = __float2bfloat16(v.w);
        __nv_bfloat16 l0 = __float2bfloat16(v.x - __bfloat162float(h0));
        __nv_bfloat16 l1 = __float2bfloat16(v.y - __bfloat162float(h1));
        __nv_bfloat16 l2 = __float2bfloat16(v.z - __bfloat162float(h2));
        __nv_bfloat16 l3 = __float2bfloat16(v.w - __bfloat162float(h3));
        *(__nv_bfloat162*)(hi + i)     = __nv_bfloat162(h0, h1);
        *(__nv_bfloat162*)(hi + i + 2) = __nv_bfloat162(h2, h3);
        *(__nv_bfloat162*)(lo + i)     = __nv_bfloat162(l0, l1);
        *(__nv_bfloat162*)(lo + i + 2) = __nv_bfloat162(l2, l3);
    }
}

// ---------------------------------------------------------------------------
// HMMA GEMM, cp.async double-buffered: C = A*B^T + bias, bf16x3 split.
// Block 128x128, K-tile 32, 8 warps (2m x 4n).
// mode 0: v=(acc+bias)*scale -> bf16 hi/lo scatter [b][h][s][dk]
// mode 1: fp32 row-major [M,N]
// ---------------------------------------------------------------------------
#define BM 128
#define BN 128
#define BK 32
#define SROW 40
#define GMAT  (BM * SROW * 2)          // 10240 B per matrix
#define GSTG  (4 * GMAT)               // 40960 B per stage
#define GEMM_SMEM (2 * GSTG)           // 81920 B

__global__ void __launch_bounds__(256, 1)
gemm_mma(const __nv_bfloat16* __restrict__ Ahi, const __nv_bfloat16* __restrict__ Alo,
         const __nv_bfloat16* __restrict__ Bhi, const __nv_bfloat16* __restrict__ Blo,
         const float* __restrict__ bias, float* __restrict__ C,
         __nv_bfloat16* __restrict__ Chi, __nv_bfloat16* __restrict__ Clo,
         float scale, int mode)
{
    extern __shared__ __nv_bfloat16 gsm[];
    const uint32_t uS = smem_u32(gsm);

    const int t = threadIdx.x;
    const int w = t >> 5, lane = t & 31;
    const int bm = blockIdx.y * BM;
    const int bn = blockIdx.x * BN;
    const int wm = (w >> 2) * 64;
    const int wn = (w & 3) * 32;

    float acc[4][4][4];
#pragma unroll
    for (int mi = 0; mi < 4; ++mi)
#pragma unroll
        for (int ni = 0; ni < 4; ++ni)
#pragma unroll
            for (int r = 0; r < 4; ++r) acc[mi][ni][r] = 0.f;

    const int aRow = wm + (lane & 15);
    const int aCol = (lane >> 4) * 8;
    const int bRowN = wn + (lane & 7) + ((lane >> 4) << 3);
    const int bColK = ((lane >> 3) & 1) * 8;

    auto issue = [&](int kt, int st) {
        const int kbase = kt * BK;
#pragma unroll
        for (int it = 0; it < 2; ++it) {
            const int c = t + it * 256;
            const int row = c >> 2;
            const int col = (c & 3) * 8;
            const uint32_t so = uS + st * GSTG + (uint32_t)(row * SROW + col) * 2;
            const size_t gA = (size_t)(bm + row) * DMODEL + kbase + col;
            const size_t gB = (size_t)(bn + row) * DMODEL + kbase + col;
            cp16(so,            Ahi + gA);
            cp16(so + GMAT,     Alo + gA);
            cp16(so + 2 * GMAT, Bhi + gB);
            cp16(so + 3 * GMAT, Blo + gB);
        }
    };

    issue(0, 0);
    CP_COMMIT();

    for (int kt = 0; kt < DMODEL / BK; ++kt) {
        const int buf = kt & 1;
        const bool more = (kt + 1) < (DMODEL / BK);
        if (more) { issue(kt + 1, buf ^ 1); CP_COMMIT(); CP_WAIT1(); }
        else      { CP_WAIT0(); }
        __syncthreads();

        const uint32_t uAhi = uS + buf * GSTG;
        const uint32_t uAlo = uAhi + GMAT;
        const uint32_t uBhi = uAhi + 2 * GMAT;
        const uint32_t uBlo = uAhi + 3 * GMAT;

#pragma unroll
        for (int ks = 0; ks < 2; ++ks) {
            const int k0 = ks * 16;
            uint32_t bhi[4][2], blo[4][2];
#pragma unroll
            for (int nb = 0; nb < 2; ++nb) {
                uint32_t r[4];
                const uint32_t off = (uint32_t)((bRowN + nb * 16) * SROW + k0 + bColK) * 2;
                ldm_x4(r, uBhi + off);
                bhi[nb * 2 + 0][0] = r[0]; bhi[nb * 2 + 0][1] = r[1];
                bhi[nb * 2 + 1][0] = r[2]; bhi[nb * 2 + 1][1] = r[3];
                ldm_x4(r, uBlo + off);
                blo[nb * 2 + 0][0] = r[0]; blo[nb * 2 + 0][1] = r[1];
                blo[nb * 2 + 1][0] = r[2]; blo[nb * 2 + 1][1] = r[3];
            }
#pragma unroll
            for (int mi = 0; mi < 4; ++mi) {
                uint32_t ahi[4], alo[4];
                const uint32_t off = (uint32_t)((aRow + mi * 16) * SROW + k0 + aCol) * 2;
                ldm_x4(ahi, uAhi + off);
                ldm_x4(alo, uAlo + off);
#pragma unroll
                for (int ni = 0; ni < 4; ++ni) {
                    mma16816(acc[mi][ni], ahi, bhi[ni]);
                    mma16816(acc[mi][ni], ahi, blo[ni]);
                    mma16816(acc[mi][ni], alo, bhi[ni]);
                }
            }
        }
        __syncthreads();
    }

    // ---- epilogue ----
    const int r0 = lane >> 2;
    const int cp = (lane & 3) * 2;
#pragma unroll
    for (int mi = 0; mi < 4; ++mi) {
#pragma unroll
        for (int ni = 0; ni < 4; ++ni) {
            const int n = bn + wn + ni * 8 + cp;
            const float2 b2 = *(const float2*)(bias + n);
#pragma unroll
            for (int half = 0; half < 2; ++half) {
                const int m = bm + wm + mi * 16 + r0 + half * 8;
                float vx = (acc[mi][ni][half * 2 + 0] + b2.x) * scale;
                float vy = (acc[mi][ni][half * 2 + 1] + b2.y) * scale;
                if (mode == 0) {
                    const int bb = m >> 11, s = m & 2047;
                    const int h = n >> 6, dd = n & 63;
                    const size_t off = (((size_t)(bb * HEADS + h) * SEQ + s) << 6) + dd;
                    __nv_bfloat16 hx = __float2bfloat16(vx);
                    __nv_bfloat16 hy = __float2bfloat16(vy);
                    *(uint32_t*)(Chi + off) = packbf(vx, vy);
                    *(uint32_t*)(Clo + off) = packbf(vx - __bfloat162float(hx),
                                                     vy - __bfloat162float(hy));
                } else {
                    float2 v; v.x = vx; v.y = vy;
                    *(float2*)(C + (size_t)m * DMODEL + n) = v;
                }
            }
        }
    }
}

// ---------------------------------------------------------------------------
// Flash attention via HMMA bf16x3, cp.async double-buffered K/V,
// ldmatrix.trans for V (stored natural [kv][d]).
// Block = 128 threads (4 warps), q-tile 64, kv-tile 64.
// Epilogue writes O hi/lo bf16 into g_Ahi/g_Alo ([b*SEQ+s][DMODEL]).
// ---------------------------------------------------------------------------
#define KS 72
#define FARR   (64 * KS * 2)                  // 9216 B per array
#define FSTG   (4 * FARR)                     // Kh,Kl,Vh,Vl per stage
#define FLASH_SMEM (2 * FARR + 2 * FSTG)      // Q(hi/lo) + 2 stages = 92160 B

__global__ void __launch_bounds__(128)
flash_mma()
{
    extern __shared__ __nv_bfloat16 fsm[];
    const uint32_t uS = smem_u32(fsm);
    const uint32_t uQh = uS, uQl = uS + FARR;
    const uint32_t uStage0 = uS + 2 * FARR;

    const int t = threadIdx.x, w = t >> 5, lane = t & 31;
    const int b = blockIdx.z, h = blockIdx.y, qb = blockIdx.x * 64;
    const size_t hb = (size_t)(b * HEADS + h) * SEQ * DK;

    const __nv_bfloat16* Qh = g_Qhi + hb + (size_t)qb * DK;
    const __nv_bfloat16* Ql = g_Qlo + hb + (size_t)qb * DK;
    const __nv_bfloat16* Khg = g_Khi + hb;
    const __nv_bfloat16* Klg = g_Klo + hb;
    const __nv_bfloat16* Vhg = g_Vhi + hb;
    const __nv_bfloat16* Vlg = g_Vlo + hb;

    // ---- load Q tile (64x64 hi/lo) ----
#pragma unroll
    for (int it = 0; it < 4; ++it) {
        const int c = t + it * 128;
        const int row = c >> 3, col = (c & 7) * 8;
        *(uint4*)&fsm[row * KS + col]            = *(const uint4*)(Qh + row * DK + col);
        *(uint4*)&fsm[64 * KS + row * KS + col]  = *(const uint4*)(Ql + row * DK + col);
    }

    // ---- cp.async issue of one kv tile into stage st ----
    auto issue = [&](int kvi, int st) {
        const __nv_bfloat16* kh = Khg + (size_t)kvi * 64 * DK;
        const __nv_bfloat16* kl = Klg + (size_t)kvi * 64 * DK;
        const __nv_bfloat16* vh = Vhg + (size_t)kvi * 64 * DK;
        const __nv_bfloat16* vl = Vlg + (size_t)kvi * 64 * DK;
        const uint32_t sb = uStage0 + st * FSTG;
#pragma unroll
        for (int it = 0; it < 4; ++it) {
            const int c = t + it * 128;
            const int row = c >> 3, col = (c & 7) * 8;
            const uint32_t so = sb + (uint32_t)(row * KS + col) * 2;
            const size_t g = (size_t)row * DK + col;
            cp16(so,            kh + g);
            cp16(so + FARR,     kl + g);
            cp16(so + 2 * FARR, vh + g);
            cp16(so + 3 * FARR, vl + g);
        }
    };

    issue(0, 0);
    CP_COMMIT();
    __syncthreads();   // Q tile visible

    // ---- Q A-fragments (persistent) ----
    uint32_t qh[4][4], ql[4][4];
    const int aRow = w * 16 + (lane & 15);
    const int aCol = (lane >> 4) * 8;
#pragma unroll
    for (int ks = 0; ks < 4; ++ks) {
        const uint32_t off = (uint32_t)(aRow * KS + ks * 16 + aCol) * 2;
        ldm_x4(qh[ks], uQh + off);
        ldm_x4(ql[ks], uQl + off);
    }

    float o[8][4];
#pragma unroll
    for (int nt = 0; nt < 8; ++nt)
#pragma unroll
        for (int r = 0; r < 4; ++r) o[nt][r] = 0.f;
    float rm0 = -1e30f, rm1 = -1e30f, rl0 = 0.f, rl1 = 0.f;

    const int bRow = (lane & 7) + ((lane >> 4) << 3);      // K (non-trans B)
    const int bCol = ((lane >> 3) & 1) * 8;
    const int vRow = (lane & 7) + (((lane >> 3) & 1) << 3); // V (trans B)
    const int vCol = (lane >> 4) * 8;

    for (int kv = 0; kv < SEQ / 64; ++kv) {
        const int buf = kv & 1;
        const bool more = (kv + 1) < (SEQ / 64);
        if (more) { issue(kv + 1, buf ^ 1); CP_COMMIT(); CP_WAIT1(); }
        else      { CP_WAIT0(); }
        __syncthreads();

        const uint32_t uKh = uStage0 + buf * FSTG;
        const uint32_t uKl = uKh + FARR;
        const uint32_t uVh = uKh + 2 * FARR;
        const uint32_t uVl = uKh + 3 * FARR;

        // ---- S = Q K^T (bf16x3) ----
        float s[8][4];
#pragma unroll
        for (int nt = 0; nt < 8; ++nt)
#pragma unroll
            for (int r = 0; r < 4; ++r) s[nt][r] = 0.f;

#pragma unroll
        for (int nb = 0; nb < 4; ++nb) {
#pragma unroll
            for (int ks = 0; ks < 4; ++ks) {
                const uint32_t off = (uint32_t)((nb * 16 + bRow) * KS + ks * 16 + bCol) * 2;
                uint32_t kbh[4], kbl[4];
                ldm_x4(kbh, uKh + off);
                ldm_x4(kbl, uKl + off);
                mma16816(s[nb * 2],     qh[ks], kbh);
                mma16816(s[nb * 2],     qh[ks], kbl);
                mma16816(s[nb * 2],     ql[ks], kbh);
                mma16816(s[nb * 2 + 1], qh[ks], kbh + 2);
                mma16816(s[nb * 2 + 1], qh[ks], kbl + 2);
                mma16816(s[nb * 2 + 1], ql[ks], kbh + 2);
            }
        }

        // ---- online softmax ----
        float mx0 = -1e30f, mx1 = -1e30f;
#pragma unroll
        for (int nt = 0; nt < 8; ++nt) {
            mx0 = fmaxf(mx0, fmaxf(s[nt][0], s[nt][1]));
            mx1 = fmaxf(mx1, fmaxf(s[nt][2], s[nt][3]));
        }
        mx0 = fmaxf(mx0, __shfl_xor_sync(0xffffffffu, mx0, 1));
        mx0 = fmaxf(mx0, __shfl_xor_sync(0xffffffffu, mx0, 2));
        mx1 = fmaxf(mx1, __shfl_xor_sync(0xffffffffu, mx1, 1));
        mx1 = fmaxf(mx1, __shfl_xor_sync(0xffffffffu, mx1, 2));
        const float nm0 = fmaxf(rm0, mx0), nm1 = fmaxf(rm1, mx1);
        const float sc0 = __expf(rm0 - nm0), sc1 = __expf(rm1 - nm1);
        rm0 = nm0; rm1 = nm1;

        float ls0 = 0.f, ls1 = 0.f;
#pragma unroll
        for (int nt = 0; nt < 8; ++nt) {
            s[nt][0] = __expf(s[nt][0] - nm0);
            s[nt][1] = __expf(s[nt][1] - nm0);
            s[nt][2] = __expf(s[nt][2] - nm1);
            s[nt][3] = __expf(s[nt][3] - nm1);
            ls0 += s[nt][0] + s[nt][1];
            ls1 += s[nt][2] + s[nt][3];
        }
        ls0 += __shfl_xor_sync(0xffffffffu, ls0, 1);
        ls0 += __shfl_xor_sync(0xffffffffu, ls0, 2);
        ls1 += __shfl_xor_sync(0xffffffffu, ls1, 1);
        ls1 += __shfl_xor_sync(0xffffffffu, ls1, 2);
        rl0 = rl0 * sc0 + ls0;
        rl1 = rl1 * sc1 + ls1;

#pragma unroll
        for (int nt = 0; nt < 8; ++nt) {
            o[nt][0] *= sc0; o[nt][1] *= sc0;
            o[nt][2] *= sc1; o[nt][3] *= sc1;
        }

        // ---- pack P hi/lo (S c-frag == P a-frag layout) ----
        uint32_t ph[4][4], pl[4][4];
#pragma unroll
        for (int j = 0; j < 4; ++j) {
            const float* p0 = s[2 * j];
            const float* p1 = s[2 * j + 1];
            ph[j][0] = packbf(p0[0], p0[1]);
            ph[j][1] = packbf(p0[2], p0[3]);
            ph[j][2] = packbf(p1[0], p1[1]);
            ph[j][3] = packbf(p1[2], p1[3]);
            float r00 = p0[0] - __bfloat162float(__float2bfloat16(p0[0]));
            float r01 = p0[1] - __bfloat162float(__float2bfloat16(p0[1]));
            float r02 = p0[2] - __bfloat162float(__float2bfloat16(p0[2]));
            float r03 = p0[3] - __bfloat162float(__float2bfloat16(p0[3]));
            float r10 = p1[0] - __bfloat162float(__float2bfloat16(p1[0]));
            float r11 = p1[1] - __bfloat162float(__float2bfloat16(p1[1]));
            float r12 = p1[2] - __bfloat162float(__float2bfloat16(p1[2]));
            float r13 = p1[3] - __bfloat162float(__float2bfloat16(p1[3]));
            pl[j][0] = packbf(r00, r01);
            pl[j][1] = packbf(r02, r03);
            pl[j][2] = packbf(r10, r11);
            pl[j][3] = packbf(r12, r13);
        }

        // ---- O += P V (bf16x3, V via ldmatrix.trans) ----
#pragma unroll
        for (int nb = 0; nb < 4; ++nb) {
#pragma unroll
            for (int ks = 0; ks < 4; ++ks) {
                const uint32_t off = (uint32_t)((ks * 16 + vRow) * KS + nb * 16 + vCol) * 2;
                uint32_t vbh[4], vbl[4];
                ldm_x4t(vbh, uVh + off);
                ldm_x4t(vbl, uVl + off);
                mma16816(o[nb * 2],     ph[ks], vbh);
                mma16816(o[nb * 2],     ph[ks], vbl);
                mma16816(o[nb * 2],     pl[ks], vbh);
                mma16816(o[nb * 2 + 1], ph[ks], vbh + 2);
                mma16816(o[nb * 2 + 1], ph[ks], vbl + 2);
                mma16816(o[nb * 2 + 1], pl[ks], vbh + 2);
            }
        }
        __syncthreads();
    }

    // ---- epilogue: normalize, write O hi/lo bf16 into g_Ahi/g_Alo ----
    const float inv0 = 1.f / rl0, inv1 = 1.f / rl1;
    const int row0 = qb + w * 16 + (lane >> 2);
    const int cbase = h * DK + 2 * (lane & 3);
    const size_t ob0 = ((size_t)b * SEQ + row0) * DMODEL;
    const size_t ob1 = ob0 + 8 * DMODEL;
#pragma unroll
    for (int nt = 0; nt < 8; ++nt) {
        float v0x = o[nt][0] * inv0, v0y = o[nt][1] * inv0;
        float v1x = o[nt][2] * inv1, v1y = o[nt][3] * inv1;
        const size_t c0 = ob0 + cbase + nt * 8;
        const size_t c1 = ob1 + cbase + nt * 8;
        *(uint32_t*)(g_Ahi + c0) = packbf(v0x, v0y);
        *(uint32_t*)(g_Ahi + c1) = packbf(v1x, v1y);
        float l0x = v0x - __bfloat162float(__float2bfloat16(v0x));
        float l0y = v0y - __bfloat162float(__float2bfloat16(v0y));
        float l1x = v1x - __bfloat162float(__float2bfloat16(v1x));
        float l1y = v1y - __bfloat162float(__float2bfloat16(v1y));
        *(uint32_t*)(g_Alo + c0) = packbf(l0x, l0y);
        *(uint32_t*)(g_Alo + c1) = packbf(l1x, l1y);
    }
}

// ---------------------------------------------------------------------------
// Launch
// ---------------------------------------------------------------------------
extern "C" void kernel_launch(void* const* d_in, const int* in_sizes, int n_in,
                              void* d_out, int out_size)
{
    const float* q  = (const float*)d_in[0];
    const float* k  = (const float*)d_in[1];
    const float* v  = (const float*)d_in[2];
    const float* Wq = (const float*)d_in[3];
    const float* bq = (const float*)d_in[4];
    const float* Wk = (const float*)d_in[5];
    const float* bk = (const float*)d_in[6];
    const float* Wv = (const float*)d_in[7];
    const float* bv = (const float*)d_in[8];
    const float* Wo = (const float*)d_in[9];
    const float* bo = (const float*)d_in[10];
    float* out = (float*)d_out;

    __nv_bfloat16 *pAhi, *pAlo, *pWhi, *pWlo;
    __nv_bfloat16 *pQh, *pQl, *pKh, *pKl, *pVh, *pVl;
    cudaGetSymbolAddress((void**)&pAhi, g_Ahi);
    cudaGetSymbolAddress((void**)&pAlo, g_Alo);
    cudaGetSymbolAddress((void**)&pWhi, g_Whi);
    cudaGetSymbolAddress((void**)&pWlo, g_Wlo);
    cudaGetSymbolAddress((void**)&pQh, g_Qhi);
    cudaGetSymbolAddress((void**)&pQl, g_Qlo);
    cudaGetSymbolAddress((void**)&pKh, g_Khi);
    cudaGetSymbolAddress((void**)&pKl, g_Klo);
    cudaGetSymbolAddress((void**)&pVh, g_Vhi);
    cudaGetSymbolAddress((void**)&pVl, g_Vlo);

    cudaFuncSetAttribute(gemm_mma, cudaFuncAttributeMaxDynamicSharedMemorySize, GEMM_SMEM);
    cudaFuncSetAttribute(flash_mma, cudaFuncAttributeMaxDynamicSharedMemorySize, FLASH_SMEM);

    const dim3 ggrid(DMODEL / BN, MROWS / BM);   // (8, 64)

    // QKV projections -> bf16 hi/lo, 1/sqrt(dk) folded into Q
    auto proj = [&](const float* act, const float* W, const float* bias,
                    __nv_bfloat16* hi, __nv_bfloat16* lo, float scale) {
        split_kernel<<<1024, 256>>>(act, pAhi, pAlo, MROWS * DMODEL);
        split_kernel<<<256, 256>>>(W, pWhi, pWlo, DMODEL * DMODEL);
        gemm_mma<<<ggrid, 256, GEMM_SMEM>>>(pAhi, pAlo, pWhi, pWlo, bias,
                                            nullptr, hi, lo, scale, 0);
    };

    proj(q, Wq, bq, pQh, pQl, 0.125f);
    proj(k, Wk, bk, pKh, pKl, 1.0f);
    proj(v, Wv, bv, pVh, pVl, 1.0f);

    const dim3 fgrid(SEQ / 64, HEADS, BATCH);    // (32, 16, 4)
    flash_mma<<<fgrid, 128, FLASH_SMEM>>>();     // writes O hi/lo to g_Ahi/g_Alo

    // output projection (reads O hi/lo directly; fp32 result)
    split_kernel<<<256, 256>>>(Wo, pWhi, pWlo, DMODEL * DMODEL);
    gemm_mma<<<ggrid, 256, GEMM_SMEM>>>(pAhi, pAlo, pWhi, pWlo, bo,
                                        out, nullptr, nullptr, 1.0f, 1);
}

// round 14
// speedup vs baseline: 3.2644x; 1.0609x over previous
#include <cuda_runtime.h>
#include <cuda_bf16.h>
#include <cstdint>

// ---------------------------------------------------------------------------
// MultiHeadAttention: B=4, H=16, S=2048, D=1024, dk=64, fp32.
// All matmul on HMMA bf16x3 split (base ISA; tcgen05 rejected by compute_103).
// R13: flash q-tile 128 (halves K/V L2 traffic), GEMM tile 128x256
// (cuts operand traffic 25%). cp.async double-buffered everywhere.
// ---------------------------------------------------------------------------

#define BATCH 4
#define HEADS 16
#define SEQ   2048
#define DMODEL 1024
#define DK    64
#define MROWS (BATCH * SEQ)        // 8192

// ---------------- scratch (__device__ globals; no allocation allowed) -------
__device__ __nv_bfloat16 g_Qhi[BATCH * HEADS * SEQ * DK];  // [b][h][s][dk]
__device__ __nv_bfloat16 g_Qlo[BATCH * HEADS * SEQ * DK];
__device__ __nv_bfloat16 g_Khi[BATCH * HEADS * SEQ * DK];
__device__ __nv_bfloat16 g_Klo[BATCH * HEADS * SEQ * DK];
__device__ __nv_bfloat16 g_Vhi[BATCH * HEADS * SEQ * DK];
__device__ __nv_bfloat16 g_Vlo[BATCH * HEADS * SEQ * DK];

__device__ __nv_bfloat16 g_Ahi[MROWS * DMODEL];   // also receives O hi from flash
__device__ __nv_bfloat16 g_Alo[MROWS * DMODEL];   // also receives O lo from flash
__device__ __nv_bfloat16 g_Whi[DMODEL * DMODEL];
__device__ __nv_bfloat16 g_Wlo[DMODEL * DMODEL];

// ---------------- helpers (base ISA) ----------------------------------------
__device__ __forceinline__ uint32_t smem_u32(const void* p) {
    uint32_t a;
    asm("{ .reg .u64 t; cvta.to.shared.u64 t, %1; cvt.u32.u64 %0, t; }" : "=r"(a) : "l"(p));
    return a;
}
__device__ __forceinline__ void ldm_x4(uint32_t* r, uint32_t addr) {
    asm volatile("ldmatrix.sync.aligned.m8n8.x4.shared.b16 {%0,%1,%2,%3}, [%4];"
                 : "=r"(r[0]), "=r"(r[1]), "=r"(r[2]), "=r"(r[3]) : "r"(addr));
}
__device__ __forceinline__ void ldm_x4t(uint32_t* r, uint32_t addr) {
    asm volatile("ldmatrix.sync.aligned.m8n8.x4.trans.shared.b16 {%0,%1,%2,%3}, [%4];"
                 : "=r"(r[0]), "=r"(r[1]), "=r"(r[2]), "=r"(r[3]) : "r"(addr));
}
__device__ __forceinline__ void mma16816(float* c, const uint32_t* a, const uint32_t* b) {
    asm volatile("mma.sync.aligned.m16n8k16.row.col.f32.bf16.bf16.f32 "
                 "{%0,%1,%2,%3}, {%4,%5,%6,%7}, {%8,%9}, {%0,%1,%2,%3};"
                 : "+f"(c[0]), "+f"(c[1]), "+f"(c[2]), "+f"(c[3])
                 : "r"(a[0]), "r"(a[1]), "r"(a[2]), "r"(a[3]), "r"(b[0]), "r"(b[1]));
}
__device__ __forceinline__ uint32_t packbf(float a, float b) {
    __nv_bfloat162 r = __floats2bfloat162_rn(a, b);
    return *(uint32_t*)&r;
}
__device__ __forceinline__ void cp16(uint32_t saddr, const void* g) {
    asm volatile("cp.async.cg.shared.global [%0], [%1], 16;" :: "r"(saddr), "l"(g));
}
#define CP_COMMIT() asm volatile("cp.async.commit_group;")
#define CP_WAIT1()  asm volatile("cp.async.wait_group 1;")
#define CP_WAIT0()  asm volatile("cp.async.wait_group 0;")

// ---------------------------------------------------------------------------
// Split kernel: fp32 -> (bf16 hi, bf16 lo)
// ---------------------------------------------------------------------------
__global__ void __launch_bounds__(256)
split_kernel(const float* __restrict__ x, __nv_bfloat16* __restrict__ hi,
             __nv_bfloat16* __restrict__ lo, int n)
{
    int i = (blockIdx.x * blockDim.x + threadIdx.x) * 4;
    const int stride = gridDim.x * blockDim.x * 4;
    for (; i < n; i += stride) {
        float4 v = *(const float4*)(x + i);
        __nv_bfloat16 h0 = __float2bfloat16(v.x);
        __nv_bfloat16 h1 = __float2bfloat16(v.y);
        __nv_bfloat16 h2 = __float2bfloat16(v.z);
        __nv_bfloat16 h3 = __float2bfloat16(v.w);
        __nv_bfloat16 l0 = __float2bfloat16(v.x - __bfloat162float(h0));
        __nv_bfloat16 l1 = __float2bfloat16(v.y - __bfloat162float(h1));
        __nv_bfloat16 l2 = __float2bfloat16(v.z - __bfloat162float(h2));
        __nv_bfloat16 l3 = __float2bfloat16(v.w - __bfloat162float(h3));
        *(__nv_bfloat162*)(hi + i)     = __nv_bfloat162(h0, h1);
        *(__nv_bfloat162*)(hi + i + 2) = __nv_bfloat162(h2, h3);
        *(__nv_bfloat162*)(lo + i)     = __nv_bfloat162(l0, l1);
        *(__nv_bfloat162*)(lo + i + 2) = __nv_bfloat162(l2, l3);
    }
}

// ---------------------------------------------------------------------------
// HMMA GEMM, cp.async double-buffered: C = A*B^T + bias, bf16x3 split.
// Block tile 128(M) x 256(N), K-tile 32, 8 warps (2m x 4n), warp tile 64x64.
// mode 0: v=(acc+bias)*scale -> bf16 hi/lo scatter [b][h][s][dk]
// mode 1: fp32 row-major [M,N]
// ---------------------------------------------------------------------------
#define BM 128
#define BN 256
#define BK 32
#define SROW 40
#define GMATA (BM * SROW * 2)          // 10240 B (A matrix)
#define GMATB (BN * SROW * 2)          // 20480 B (B matrix)
#define GSTG  (2 * GMATA + 2 * GMATB)  // 61440 B per stage
#define GEMM_SMEM (2 * GSTG)           // 122880 B

__global__ void __launch_bounds__(256, 1)
gemm_mma(const __nv_bfloat16* __restrict__ Ahi, const __nv_bfloat16* __restrict__ Alo,
         const __nv_bfloat16* __restrict__ Bhi, const __nv_bfloat16* __restrict__ Blo,
         const float* __restrict__ bias, float* __restrict__ C,
         __nv_bfloat16* __restrict__ Chi, __nv_bfloat16* __restrict__ Clo,
         float scale, int mode)
{
    extern __shared__ __nv_bfloat16 gsm[];
    const uint32_t uS = smem_u32(gsm);

    const int t = threadIdx.x;
    const int w = t >> 5, lane = t & 31;
    const int bm = blockIdx.y * BM;
    const int bn = blockIdx.x * BN;
    const int wm = (w >> 2) * 64;      // 0 / 64
    const int wn = (w & 3) * 64;       // 0 / 64 / 128 / 192

    float acc[4][8][4];
#pragma unroll
    for (int mi = 0; mi < 4; ++mi)
#pragma unroll
        for (int ni = 0; ni < 8; ++ni)
#pragma unroll
            for (int r = 0; r < 4; ++r) acc[mi][ni][r] = 0.f;

    const int aRow = wm + (lane & 15);
    const int aCol = (lane >> 4) * 8;
    const int bRowN = wn + (lane & 7) + ((lane >> 4) << 3);
    const int bColK = ((lane >> 3) & 1) * 8;

    auto issue = [&](int kt, int st) {
        const int kbase = kt * BK;
        const uint32_t sb = uS + st * GSTG;
        // A: 128x32 hi/lo (512 16B-chunks each)
#pragma unroll
        for (int it = 0; it < 2; ++it) {
            const int c = t + it * 256;
            const int row = c >> 2;
            const int col = (c & 3) * 8;
            const uint32_t so = sb + (uint32_t)(row * SROW + col) * 2;
            const size_t gA = (size_t)(bm + row) * DMODEL + kbase + col;
            cp16(so,         Ahi + gA);
            cp16(so + GMATA, Alo + gA);
        }
        // B: 256x32 hi/lo (1024 16B-chunks each)
#pragma unroll
        for (int it = 0; it < 4; ++it) {
            const int c = t + it * 256;
            const int row = c >> 2;
            const int col = (c & 3) * 8;
            const uint32_t so = sb + 2 * GMATA + (uint32_t)(row * SROW + col) * 2;
            const size_t gB = (size_t)(bn + row) * DMODEL + kbase + col;
            cp16(so,         Bhi + gB);
            cp16(so + GMATB, Blo + gB);
        }
    };

    issue(0, 0);
    CP_COMMIT();

    for (int kt = 0; kt < DMODEL / BK; ++kt) {
        const int buf = kt & 1;
        const bool more = (kt + 1) < (DMODEL / BK);
        if (more) { issue(kt + 1, buf ^ 1); CP_COMMIT(); CP_WAIT1(); }
        else      { CP_WAIT0(); }
        __syncthreads();

        const uint32_t uAhi = uS + buf * GSTG;
        const uint32_t uAlo = uAhi + GMATA;
        const uint32_t uBhi = uAhi + 2 * GMATA;
        const uint32_t uBlo = uBhi + GMATB;

#pragma unroll
        for (int ks = 0; ks < 2; ++ks) {
            const int k0 = ks * 16;
            uint32_t bhi[8][2], blo[8][2];
#pragma unroll
            for (int nb = 0; nb < 4; ++nb) {
                uint32_t r[4];
                const uint32_t off = (uint32_t)((bRowN + nb * 16) * SROW + k0 + bColK) * 2;
                ldm_x4(r, uBhi + off);
                bhi[nb * 2 + 0][0] = r[0]; bhi[nb * 2 + 0][1] = r[1];
                bhi[nb * 2 + 1][0] = r[2]; bhi[nb * 2 + 1][1] = r[3];
                ldm_x4(r, uBlo + off);
                blo[nb * 2 + 0][0] = r[0]; blo[nb * 2 + 0][1] = r[1];
                blo[nb * 2 + 1][0] = r[2]; blo[nb * 2 + 1][1] = r[3];
            }
#pragma unroll
            for (int mi = 0; mi < 4; ++mi) {
                uint32_t ahi[4], alo[4];
                const uint32_t off = (uint32_t)((aRow + mi * 16) * SROW + k0 + aCol) * 2;
                ldm_x4(ahi, uAhi + off);
                ldm_x4(alo, uAlo + off);
#pragma unroll
                for (int ni = 0; ni < 8; ++ni) {
                    mma16816(acc[mi][ni], ahi, bhi[ni]);
                    mma16816(acc[mi][ni], ahi, blo[ni]);
                    mma16816(acc[mi][ni], alo, bhi[ni]);
                }
            }
        }
        __syncthreads();
    }

    // ---- epilogue ----
    const int r0 = lane >> 2;
    const int cp = (lane & 3) * 2;
#pragma unroll
    for (int mi = 0; mi < 4; ++mi) {
#pragma unroll
        for (int ni = 0; ni < 8; ++ni) {
            const int n = bn + wn + ni * 8 + cp;
            const float2 b2 = *(const float2*)(bias + n);
#pragma unroll
            for (int half = 0; half < 2; ++half) {
                const int m = bm + wm + mi * 16 + r0 + half * 8;
                float vx = (acc[mi][ni][half * 2 + 0] + b2.x) * scale;
                float vy = (acc[mi][ni][half * 2 + 1] + b2.y) * scale;
                if (mode == 0) {
                    const int bb = m >> 11, s = m & 2047;
                    const int h = n >> 6, dd = n & 63;
                    const size_t off = (((size_t)(bb * HEADS + h) * SEQ + s) << 6) + dd;
                    __nv_bfloat16 hx = __float2bfloat16(vx);
                    __nv_bfloat16 hy = __float2bfloat16(vy);
                    *(uint32_t*)(Chi + off) = packbf(vx, vy);
                    *(uint32_t*)(Clo + off) = packbf(vx - __bfloat162float(hx),
                                                     vy - __bfloat162float(hy));
                } else {
                    float2 v; v.x = vx; v.y = vy;
                    *(float2*)(C + (size_t)m * DMODEL + n) = v;
                }
            }
        }
    }
}

// ---------------------------------------------------------------------------
// Flash attention via HMMA bf16x3, cp.async double-buffered K/V,
// ldmatrix.trans for V. Block = 256 threads (8 warps), q-tile 128
// (warp w owns rows w*16..w*16+15), kv-tile 64.
// Epilogue writes O hi/lo bf16 into g_Ahi/g_Alo ([b*SEQ+s][DMODEL]).
// ---------------------------------------------------------------------------
#define KS 72
#define FARR   (64 * KS * 2)                   // 9216 B per K/V array
#define FQARR  (128 * KS * 2)                  // 18432 B per Q array
#define FSTG   (4 * FARR)                      // Kh,Kl,Vh,Vl per stage
#define FLASH_SMEM (2 * FQARR + 2 * FSTG)      // 110592 B

__global__ void __launch_bounds__(256)
flash_mma()
{
    extern __shared__ __nv_bfloat16 fsm[];
    const uint32_t uS = smem_u32(fsm);
    const uint32_t uQh = uS, uQl = uS + FQARR;
    const uint32_t uStage0 = uS + 2 * FQARR;

    const int t = threadIdx.x, w = t >> 5, lane = t & 31;
    const int b = blockIdx.z, h = blockIdx.y, qb = blockIdx.x * 128;
    const size_t hb = (size_t)(b * HEADS + h) * SEQ * DK;

    const __nv_bfloat16* Qh = g_Qhi + hb + (size_t)qb * DK;
    const __nv_bfloat16* Ql = g_Qlo + hb + (size_t)qb * DK;
    const __nv_bfloat16* Khg = g_Khi + hb;
    const __nv_bfloat16* Klg = g_Klo + hb;
    const __nv_bfloat16* Vhg = g_Vhi + hb;
    const __nv_bfloat16* Vlg = g_Vlo + hb;

    // ---- load Q tile (128x64 hi/lo) ----
#pragma unroll
    for (int it = 0; it < 4; ++it) {
        const int c = t + it * 256;
        const int row = c >> 3, col = (c & 7) * 8;
        *(uint4*)&fsm[row * KS + col]             = *(const uint4*)(Qh + row * DK + col);
        *(uint4*)&fsm[128 * KS + row * KS + col]  = *(const uint4*)(Ql + row * DK + col);
    }

    // ---- cp.async issue of one kv tile into stage st ----
    auto issue = [&](int kvi, int st) {
        const __nv_bfloat16* kh = Khg + (size_t)kvi * 64 * DK;
        const __nv_bfloat16* kl = Klg + (size_t)kvi * 64 * DK;
        const __nv_bfloat16* vh = Vhg + (size_t)kvi * 64 * DK;
        const __nv_bfloat16* vl = Vlg + (size_t)kvi * 64 * DK;
        const uint32_t sb = uStage0 + st * FSTG;
#pragma unroll
        for (int it = 0; it < 2; ++it) {
            const int c = t + it * 256;
            const int row = c >> 3, col = (c & 7) * 8;
            const uint32_t so = sb + (uint32_t)(row * KS + col) * 2;
            const size_t g = (size_t)row * DK + col;
            cp16(so,            kh + g);
            cp16(so + FARR,     kl + g);
            cp16(so + 2 * FARR, vh + g);
            cp16(so + 3 * FARR, vl + g);
        }
    };

    issue(0, 0);
    CP_COMMIT();
    __syncthreads();   // Q tile visible

    // ---- Q A-fragments (persistent) ----
    uint32_t qh[4][4], ql[4][4];
    const int aRow = w * 16 + (lane & 15);
    const int aCol = (lane >> 4) * 8;
#pragma unroll
    for (int ks = 0; ks < 4; ++ks) {
        const uint32_t off = (uint32_t)(aRow * KS + ks * 16 + aCol) * 2;
        ldm_x4(qh[ks], uQh + off);
        ldm_x4(ql[ks], uQl + off);
    }

    float o[8][4];
#pragma unroll
    for (int nt = 0; nt < 8; ++nt)
#pragma unroll
        for (int r = 0; r < 4; ++r) o[nt][r] = 0.f;
    float rm0 = -1e30f, rm1 = -1e30f, rl0 = 0.f, rl1 = 0.f;

    const int bRow = (lane & 7) + ((lane >> 4) << 3);       // K (non-trans B)
    const int bCol = ((lane >> 3) & 1) * 8;
    const int vRow = (lane & 7) + (((lane >> 3) & 1) << 3); // V (trans B)
    const int vCol = (lane >> 4) * 8;

    for (int kv = 0; kv < SEQ / 64; ++kv) {
        const int buf = kv & 1;
        const bool more = (kv + 1) < (SEQ / 64);
        if (more) { issue(kv + 1, buf ^ 1); CP_COMMIT(); CP_WAIT1(); }
        else      { CP_WAIT0(); }
        __syncthreads();

        const uint32_t uKh = uStage0 + buf * FSTG;
        const uint32_t uKl = uKh + FARR;
        const uint32_t uVh = uKh + 2 * FARR;
        const uint32_t uVl = uKh + 3 * FARR;

        // ---- S = Q K^T (bf16x3) ----
        float s[8][4];
#pragma unroll
        for (int nt = 0; nt < 8; ++nt)
#pragma unroll
            for (int r = 0; r < 4; ++r) s[nt][r] = 0.f;

#pragma unroll
        for (int nb = 0; nb < 4; ++nb) {
#pragma unroll
            for (int ks = 0; ks < 4; ++ks) {
                const uint32_t off = (uint32_t)((nb * 16 + bRow) * KS + ks * 16 + bCol) * 2;
                uint32_t kbh[4], kbl[4];
                ldm_x4(kbh, uKh + off);
                ldm_x4(kbl, uKl + off);
                mma16816(s[nb * 2],     qh[ks], kbh);
                mma16816(s[nb * 2],     qh[ks], kbl);
                mma16816(s[nb * 2],     ql[ks], kbh);
                mma16816(s[nb * 2 + 1], qh[ks], kbh + 2);
                mma16816(s[nb * 2 + 1], qh[ks], kbl + 2);
                mma16816(s[nb * 2 + 1], ql[ks], kbh + 2);
            }
        }

        // ---- online softmax (rows lane/4 and lane/4+8; stats across 4 lanes) ----
        float mx0 = -1e30f, mx1 = -1e30f;
#pragma unroll
        for (int nt = 0; nt < 8; ++nt) {
            mx0 = fmaxf(mx0, fmaxf(s[nt][0], s[nt][1]));
            mx1 = fmaxf(mx1, fmaxf(s[nt][2], s[nt][3]));
        }
        mx0 = fmaxf(mx0, __shfl_xor_sync(0xffffffffu, mx0, 1));
        mx0 = fmaxf(mx0, __shfl_xor_sync(0xffffffffu, mx0, 2));
        mx1 = fmaxf(mx1, __shfl_xor_sync(0xffffffffu, mx1, 1));
        mx1 = fmaxf(mx1, __shfl_xor_sync(0xffffffffu, mx1, 2));
        const float nm0 = fmaxf(rm0, mx0), nm1 = fmaxf(rm1, mx1);
        const float sc0 = __expf(rm0 - nm0), sc1 = __expf(rm1 - nm1);
        rm0 = nm0; rm1 = nm1;

        float ls0 = 0.f, ls1 = 0.f;
#pragma unroll
        for (int nt = 0; nt < 8; ++nt) {
            s[nt][0] = __expf(s[nt][0] - nm0);
            s[nt][1] = __expf(s[nt][1] - nm0);
            s[nt][2] = __expf(s[nt][2] - nm1);
            s[nt][3] = __expf(s[nt][3] - nm1);
            ls0 += s[nt][0] + s[nt][1];
            ls1 += s[nt][2] + s[nt][3];
        }
        ls0 += __shfl_xor_sync(0xffffffffu, ls0, 1);
        ls0 += __shfl_xor_sync(0xffffffffu, ls0, 2);
        ls1 += __shfl_xor_sync(0xffffffffu, ls1, 1);
        ls1 += __shfl_xor_sync(0xffffffffu, ls1, 2);
        rl0 = rl0 * sc0 + ls0;
        rl1 = rl1 * sc1 + ls1;

#pragma unroll
        for (int nt = 0; nt < 8; ++nt) {
            o[nt][0] *= sc0; o[nt][1] *= sc0;
            o[nt][2] *= sc1; o[nt][3] *= sc1;
        }

        // ---- pack P hi/lo (S c-frag == P a-frag layout) ----
        uint32_t ph[4][4], pl[4][4];
#pragma unroll
        for (int j = 0; j < 4; ++j) {
            const float* p0 = s[2 * j];
            const float* p1 = s[2 * j + 1];
            ph[j][0] = packbf(p0[0], p0[1]);
            ph[j][1] = packbf(p0[2], p0[3]);
            ph[j][2] = packbf(p1[0], p1[1]);
            ph[j][3] = packbf(p1[2], p1[3]);
            float r00 = p0[0] - __bfloat162float(__float2bfloat16(p0[0]));
            float r01 = p0[1] - __bfloat162float(__float2bfloat16(p0[1]));
            float r02 = p0[2] - __bfloat162float(__float2bfloat16(p0[2]));
            float r03 = p0[3] - __bfloat162float(__float2bfloat16(p0[3]));
            float r10 = p1[0] - __bfloat162float(__float2bfloat16(p1[0]));
            float r11 = p1[1] - __bfloat162float(__float2bfloat16(p1[1]));
            float r12 = p1[2] - __bfloat162float(__float2bfloat16(p1[2]));
            float r13 = p1[3] - __bfloat162float(__float2bfloat16(p1[3]));
            pl[j][0] = packbf(r00, r01);
            pl[j][1] = packbf(r02, r03);
            pl[j][2] = packbf(r10, r11);
            pl[j][3] = packbf(r12, r13);
        }

        // ---- O += P V (bf16x3, V via ldmatrix.trans) ----
#pragma unroll
        for (int nb = 0; nb < 4; ++nb) {
#pragma unroll
            for (int ks = 0; ks < 4; ++ks) {
                const uint32_t off = (uint32_t)((ks * 16 + vRow) * KS + nb * 16 + vCol) * 2;
                uint32_t vbh[4], vbl[4];
                ldm_x4t(vbh, uVh + off);
                ldm_x4t(vbl, uVl + off);
                mma16816(o[nb * 2],     ph[ks], vbh);
                mma16816(o[nb * 2],     ph[ks], vbl);
                mma16816(o[nb * 2],     pl[ks], vbh);
                mma16816(o[nb * 2 + 1], ph[ks], vbh + 2);
                mma16816(o[nb * 2 + 1], ph[ks], vbl + 2);
                mma16816(o[nb * 2 + 1], pl[ks], vbh + 2);
            }
        }
        __syncthreads();
    }

    // ---- epilogue: normalize, write O hi/lo bf16 into g_Ahi/g_Alo ----
    const float inv0 = 1.f / rl0, inv1 = 1.f / rl1;
    const int row0 = qb + w * 16 + (lane >> 2);
    const int cbase = h * DK + 2 * (lane & 3);
    const size_t ob0 = ((size_t)b * SEQ + row0) * DMODEL;
    const size_t ob1 = ob0 + 8 * DMODEL;
#pragma unroll
    for (int nt = 0; nt < 8; ++nt) {
        float v0x = o[nt][0] * inv0, v0y = o[nt][1] * inv0;
        float v1x = o[nt][2] * inv1, v1y = o[nt][3] * inv1;
        const size_t c0 = ob0 + cbase + nt * 8;
        const size_t c1 = ob1 + cbase + nt * 8;
        *(uint32_t*)(g_Ahi + c0) = packbf(v0x, v0y);
        *(uint32_t*)(g_Ahi + c1) = packbf(v1x, v1y);
        float l0x = v0x - __bfloat162float(__float2bfloat16(v0x));
        float l0y = v0y - __bfloat162float(__float2bfloat16(v0y));
        float l1x = v1x - __bfloat162float(__float2bfloat16(v1x));
        float l1y = v1y - __bfloat162float(__float2bfloat16(v1y));
        *(uint32_t*)(g_Alo + c0) = packbf(l0x, l0y);
        *(uint32_t*)(g_Alo + c1) = packbf(l1x, l1y);
    }
}

// ---------------------------------------------------------------------------
// Launch
// ---------------------------------------------------------------------------
extern "C" void kernel_launch(void* const* d_in, const int* in_sizes, int n_in,
                              void* d_out, int out_size)
{
    const float* q  = (const float*)d_in[0];
    const float* k  = (const float*)d_in[1];
    const float* v  = (const float*)d_in[2];
    const float* Wq = (const float*)d_in[3];
    const float* bq = (const float*)d_in[4];
    const float* Wk = (const float*)d_in[5];
    const float* bk = (const float*)d_in[6];
    const float* Wv = (const float*)d_in[7];
    const float* bv = (const float*)d_in[8];
    const float* Wo = (const float*)d_in[9];
    const float* bo = (const float*)d_in[10];
    float* out = (float*)d_out;

    __nv_bfloat16 *pAhi, *pAlo, *pWhi, *pWlo;
    __nv_bfloat16 *pQh, *pQl, *pKh, *pKl, *pVh, *pVl;
    cudaGetSymbolAddress((void**)&pAhi, g_Ahi);
    cudaGetSymbolAddress((void**)&pAlo, g_Alo);
    cudaGetSymbolAddress((void**)&pWhi, g_Whi);
    cudaGetSymbolAddress((void**)&pWlo, g_Wlo);
    cudaGetSymbolAddress((void**)&pQh, g_Qhi);
    cudaGetSymbolAddress((void**)&pQl, g_Qlo);
    cudaGetSymbolAddress((void**)&pKh, g_Khi);
    cudaGetSymbolAddress((void**)&pKl, g_Klo);
    cudaGetSymbolAddress((void**)&pVh, g_Vhi);
    cudaGetSymbolAddress((void**)&pVl, g_Vlo);

    cudaFuncSetAttribute(gemm_mma, cudaFuncAttributeMaxDynamicSharedMemorySize, GEMM_SMEM);
    cudaFuncSetAttribute(flash_mma, cudaFuncAttributeMaxDynamicSharedMemorySize, FLASH_SMEM);

    const dim3 ggrid(DMODEL / BN, MROWS / BM);   // (4, 64)

    // QKV projections -> bf16 hi/lo, 1/sqrt(dk) folded into Q
    auto proj = [&](const float* act, const float* W, const float* bias,
                    __nv_bfloat16* hi, __nv_bfloat16* lo, float scale) {
        split_kernel<<<1024, 256>>>(act, pAhi, pAlo, MROWS * DMODEL);
        split_kernel<<<256, 256>>>(W, pWhi, pWlo, DMODEL * DMODEL);
        gemm_mma<<<ggrid, 256, GEMM_SMEM>>>(pAhi, pAlo, pWhi, pWlo, bias,
                                            nullptr, hi, lo, scale, 0);
    };

    proj(q, Wq, bq, pQh, pQl, 0.125f);
    proj(k, Wk, bk, pKh, pKl, 1.0f);
    proj(v, Wv, bv, pVh, pVl, 1.0f);

    const dim3 fgrid(SEQ / 128, HEADS, BATCH);   // (16, 16, 4)
    flash_mma<<<fgrid, 256, FLASH_SMEM>>>();     // writes O hi/lo to g_Ahi/g_Alo

    // output projection (reads O hi/lo directly; fp32 result)
    split_kernel<<<256, 256>>>(Wo, pWhi, pWlo, DMODEL * DMODEL);
    gemm_mma<<<ggrid, 256, GEMM_SMEM>>>(pAhi, pAlo, pWhi, pWlo, bo,
                                        out, nullptr, nullptr, 1.0f, 1);
}

// round 15
// speedup vs baseline: 3.3362x; 1.0220x over previous
#include <cuda_runtime.h>
#include <cuda_bf16.h>
#include <cstdint>

// ---------------------------------------------------------------------------
// MultiHeadAttention: B=4, H=16, S=2048, D=1024, dk=64, fp32.
// All matmul on HMMA bf16x3 split (base ISA; tcgen05 rejected by compute_103).
// R15: flash mma loops reordered ks-outer/nb-inner (8 independent accumulator
// chains instead of 2 -> kills RAW stalls on the tensor pipe); softmax in
// log2 domain (log2e folded into Q scale, bare exp2f).
// ---------------------------------------------------------------------------

#define BATCH 4
#define HEADS 16
#define SEQ   2048
#define DMODEL 1024
#define DK    64
#define MROWS (BATCH * SEQ)        // 8192

// ---------------- scratch (__device__ globals; no allocation allowed) -------
__device__ __nv_bfloat16 g_Qhi[BATCH * HEADS * SEQ * DK];  // [b][h][s][dk]
__device__ __nv_bfloat16 g_Qlo[BATCH * HEADS * SEQ * DK];
__device__ __nv_bfloat16 g_Khi[BATCH * HEADS * SEQ * DK];
__device__ __nv_bfloat16 g_Klo[BATCH * HEADS * SEQ * DK];
__device__ __nv_bfloat16 g_Vhi[BATCH * HEADS * SEQ * DK];
__device__ __nv_bfloat16 g_Vlo[BATCH * HEADS * SEQ * DK];

__device__ __nv_bfloat16 g_Ahi[MROWS * DMODEL];   // also receives O hi from flash
__device__ __nv_bfloat16 g_Alo[MROWS * DMODEL];   // also receives O lo from flash
__device__ __nv_bfloat16 g_Whi[DMODEL * DMODEL];
__device__ __nv_bfloat16 g_Wlo[DMODEL * DMODEL];

// ---------------- helpers (base ISA) ----------------------------------------
__device__ __forceinline__ uint32_t smem_u32(const void* p) {
    uint32_t a;
    asm("{ .reg .u64 t; cvta.to.shared.u64 t, %1; cvt.u32.u64 %0, t; }" : "=r"(a) : "l"(p));
    return a;
}
__device__ __forceinline__ void ldm_x4(uint32_t* r, uint32_t addr) {
    asm volatile("ldmatrix.sync.aligned.m8n8.x4.shared.b16 {%0,%1,%2,%3}, [%4];"
                 : "=r"(r[0]), "=r"(r[1]), "=r"(r[2]), "=r"(r[3]) : "r"(addr));
}
__device__ __forceinline__ void ldm_x4t(uint32_t* r, uint32_t addr) {
    asm volatile("ldmatrix.sync.aligned.m8n8.x4.trans.shared.b16 {%0,%1,%2,%3}, [%4];"
                 : "=r"(r[0]), "=r"(r[1]), "=r"(r[2]), "=r"(r[3]) : "r"(addr));
}
__device__ __forceinline__ void mma16816(float* c, const uint32_t* a, const uint32_t* b) {
    asm volatile("mma.sync.aligned.m16n8k16.row.col.f32.bf16.bf16.f32 "
                 "{%0,%1,%2,%3}, {%4,%5,%6,%7}, {%8,%9}, {%0,%1,%2,%3};"
                 : "+f"(c[0]), "+f"(c[1]), "+f"(c[2]), "+f"(c[3])
                 : "r"(a[0]), "r"(a[1]), "r"(a[2]), "r"(a[3]), "r"(b[0]), "r"(b[1]));
}
__device__ __forceinline__ uint32_t packbf(float a, float b) {
    __nv_bfloat162 r = __floats2bfloat162_rn(a, b);
    return *(uint32_t*)&r;
}
__device__ __forceinline__ void cp16(uint32_t saddr, const void* g) {
    asm volatile("cp.async.cg.shared.global [%0], [%1], 16;" :: "r"(saddr), "l"(g));
}
#define CP_COMMIT() asm volatile("cp.async.commit_group;")
#define CP_WAIT1()  asm volatile("cp.async.wait_group 1;")
#define CP_WAIT0()  asm volatile("cp.async.wait_group 0;")

// ---------------------------------------------------------------------------
// Split kernel: fp32 -> (bf16 hi, bf16 lo)
// ---------------------------------------------------------------------------
__global__ void __launch_bounds__(256)
split_kernel(const float* __restrict__ x, __nv_bfloat16* __restrict__ hi,
             __nv_bfloat16* __restrict__ lo, int n)
{
    int i = (blockIdx.x * blockDim.x + threadIdx.x) * 4;
    const int stride = gridDim.x * blockDim.x * 4;
    for (; i < n; i += stride) {
        float4 v = *(const float4*)(x + i);
        __nv_bfloat16 h0 = __float2bfloat16(v.x);
        __nv_bfloat16 h1 = __float2bfloat16(v.y);
        __nv_bfloat16 h2 = __float2bfloat16(v.z);
        __nv_bfloat16 h3 = __float2bfloat16(v.w);
        __nv_bfloat16 l0 = __float2bfloat16(v.x - __bfloat162float(h0));
        __nv_bfloat16 l1 = __float2bfloat16(v.y - __bfloat162float(h1));
        __nv_bfloat16 l2 = __float2bfloat16(v.z - __bfloat162float(h2));
        __nv_bfloat16 l3 = __float2bfloat16(v.w - __bfloat162float(h3));
        *(__nv_bfloat162*)(hi + i)     = __nv_bfloat162(h0, h1);
        *(__nv_bfloat162*)(hi + i + 2) = __nv_bfloat162(h2, h3);
        *(__nv_bfloat162*)(lo + i)     = __nv_bfloat162(l0, l1);
        *(__nv_bfloat162*)(lo + i + 2) = __nv_bfloat162(l2, l3);
    }
}

// ---------------------------------------------------------------------------
// HMMA GEMM, cp.async double-buffered: C = A*B^T + bias, bf16x3 split.
// Block tile 128(M) x 256(N), K-tile 32, 8 warps (2m x 4n), warp tile 64x64.
// mode 0: v=(acc+bias)*scale -> bf16 hi/lo scatter [b][h][s][dk]
// mode 1: fp32 row-major [M,N]
// ---------------------------------------------------------------------------
#define BM 128
#define BN 256
#define BK 32
#define SROW 40
#define GMATA (BM * SROW * 2)          // 10240 B (A matrix)
#define GMATB (BN * SROW * 2)          // 20480 B (B matrix)
#define GSTG  (2 * GMATA + 2 * GMATB)  // 61440 B per stage
#define GEMM_SMEM (2 * GSTG)           // 122880 B

__global__ void __launch_bounds__(256, 1)
gemm_mma(const __nv_bfloat16* __restrict__ Ahi, const __nv_bfloat16* __restrict__ Alo,
         const __nv_bfloat16* __restrict__ Bhi, const __nv_bfloat16* __restrict__ Blo,
         const float* __restrict__ bias, float* __restrict__ C,
         __nv_bfloat16* __restrict__ Chi, __nv_bfloat16* __restrict__ Clo,
         float scale, int mode)
{
    extern __shared__ __nv_bfloat16 gsm[];
    const uint32_t uS = smem_u32(gsm);

    const int t = threadIdx.x;
    const int w = t >> 5, lane = t & 31;
    const int bm = blockIdx.y * BM;
    const int bn = blockIdx.x * BN;
    const int wm = (w >> 2) * 64;      // 0 / 64
    const int wn = (w & 3) * 64;       // 0 / 64 / 128 / 192

    float acc[4][8][4];
#pragma unroll
    for (int mi = 0; mi < 4; ++mi)
#pragma unroll
        for (int ni = 0; ni < 8; ++ni)
#pragma unroll
            for (int r = 0; r < 4; ++r) acc[mi][ni][r] = 0.f;

    const int aRow = wm + (lane & 15);
    const int aCol = (lane >> 4) * 8;
    const int bRowN = wn + (lane & 7) + ((lane >> 4) << 3);
    const int bColK = ((lane >> 3) & 1) * 8;

    auto issue = [&](int kt, int st) {
        const int kbase = kt * BK;
        const uint32_t sb = uS + st * GSTG;
#pragma unroll
        for (int it = 0; it < 2; ++it) {
            const int c = t + it * 256;
            const int row = c >> 2;
            const int col = (c & 3) * 8;
            const uint32_t so = sb + (uint32_t)(row * SROW + col) * 2;
            const size_t gA = (size_t)(bm + row) * DMODEL + kbase + col;
            cp16(so,         Ahi + gA);
            cp16(so + GMATA, Alo + gA);
        }
#pragma unroll
        for (int it = 0; it < 4; ++it) {
            const int c = t + it * 256;
            const int row = c >> 2;
            const int col = (c & 3) * 8;
            const uint32_t so = sb + 2 * GMATA + (uint32_t)(row * SROW + col) * 2;
            const size_t gB = (size_t)(bn + row) * DMODEL + kbase + col;
            cp16(so,         Bhi + gB);
            cp16(so + GMATB, Blo + gB);
        }
    };

    issue(0, 0);
    CP_COMMIT();

    for (int kt = 0; kt < DMODEL / BK; ++kt) {
        const int buf = kt & 1;
        const bool more = (kt + 1) < (DMODEL / BK);
        if (more) { issue(kt + 1, buf ^ 1); CP_COMMIT(); CP_WAIT1(); }
        else      { CP_WAIT0(); }
        __syncthreads();

        const uint32_t uAhi = uS + buf * GSTG;
        const uint32_t uAlo = uAhi + GMATA;
        const uint32_t uBhi = uAhi + 2 * GMATA;
        const uint32_t uBlo = uBhi + GMATB;

#pragma unroll
        for (int ks = 0; ks < 2; ++ks) {
            const int k0 = ks * 16;
            uint32_t bhi[8][2], blo[8][2];
#pragma unroll
            for (int nb = 0; nb < 4; ++nb) {
                uint32_t r[4];
                const uint32_t off = (uint32_t)((bRowN + nb * 16) * SROW + k0 + bColK) * 2;
                ldm_x4(r, uBhi + off);
                bhi[nb * 2 + 0][0] = r[0]; bhi[nb * 2 + 0][1] = r[1];
                bhi[nb * 2 + 1][0] = r[2]; bhi[nb * 2 + 1][1] = r[3];
                ldm_x4(r, uBlo + off);
                blo[nb * 2 + 0][0] = r[0]; blo[nb * 2 + 0][1] = r[1];
                blo[nb * 2 + 1][0] = r[2]; blo[nb * 2 + 1][1] = r[3];
            }
#pragma unroll
            for (int mi = 0; mi < 4; ++mi) {
                uint32_t ahi[4], alo[4];
                const uint32_t off = (uint32_t)((aRow + mi * 16) * SROW + k0 + aCol) * 2;
                ldm_x4(ahi, uAhi + off);
                ldm_x4(alo, uAlo + off);
#pragma unroll
                for (int ni = 0; ni < 8; ++ni) {
                    mma16816(acc[mi][ni], ahi, bhi[ni]);
                    mma16816(acc[mi][ni], ahi, blo[ni]);
                    mma16816(acc[mi][ni], alo, bhi[ni]);
                }
            }
        }
        __syncthreads();
    }

    // ---- epilogue ----
    const int r0 = lane >> 2;
    const int cp = (lane & 3) * 2;
#pragma unroll
    for (int mi = 0; mi < 4; ++mi) {
#pragma unroll
        for (int ni = 0; ni < 8; ++ni) {
            const int n = bn + wn + ni * 8 + cp;
            const float2 b2 = *(const float2*)(bias + n);
#pragma unroll
            for (int half = 0; half < 2; ++half) {
                const int m = bm + wm + mi * 16 + r0 + half * 8;
                float vx = (acc[mi][ni][half * 2 + 0] + b2.x) * scale;
                float vy = (acc[mi][ni][half * 2 + 1] + b2.y) * scale;
                if (mode == 0) {
                    const int bb = m >> 11, s = m & 2047;
                    const int h = n >> 6, dd = n & 63;
                    const size_t off = (((size_t)(bb * HEADS + h) * SEQ + s) << 6) + dd;
                    __nv_bfloat16 hx = __float2bfloat16(vx);
                    __nv_bfloat16 hy = __float2bfloat16(vy);
                    *(uint32_t*)(Chi + off) = packbf(vx, vy);
                    *(uint32_t*)(Clo + off) = packbf(vx - __bfloat162float(hx),
                                                     vy - __bfloat162float(hy));
                } else {
                    float2 v; v.x = vx; v.y = vy;
                    *(float2*)(C + (size_t)m * DMODEL + n) = v;
                }
            }
        }
    }
}

// ---------------------------------------------------------------------------
// Flash attention via HMMA bf16x3, cp.async double-buffered K/V,
// ldmatrix.trans for V. Block = 256 threads (8 warps), q-tile 128,
// kv-tile 64. Scores arrive in the LOG2 domain (log2e folded into Q scale);
// softmax uses bare exp2f. mma loops are ks-outer / nb-inner so 8 independent
// accumulator chains are in flight (RAW-stall free).
// Epilogue writes O hi/lo bf16 into g_Ahi/g_Alo ([b*SEQ+s][DMODEL]).
// ---------------------------------------------------------------------------
#define KS 72
#define FARR   (64 * KS * 2)                   // 9216 B per K/V array
#define FQARR  (128 * KS * 2)                  // 18432 B per Q array
#define FSTG   (4 * FARR)                      // Kh,Kl,Vh,Vl per stage
#define FLASH_SMEM (2 * FQARR + 2 * FSTG)      // 110592 B

__global__ void __launch_bounds__(256)
flash_mma()
{
    extern __shared__ __nv_bfloat16 fsm[];
    const uint32_t uS = smem_u32(fsm);
    const uint32_t uQh = uS, uQl = uS + FQARR;
    const uint32_t uStage0 = uS + 2 * FQARR;

    const int t = threadIdx.x, w = t >> 5, lane = t & 31;
    const int b = blockIdx.z, h = blockIdx.y, qb = blockIdx.x * 128;
    const size_t hb = (size_t)(b * HEADS + h) * SEQ * DK;

    const __nv_bfloat16* Qh = g_Qhi + hb + (size_t)qb * DK;
    const __nv_bfloat16* Ql = g_Qlo + hb + (size_t)qb * DK;
    const __nv_bfloat16* Khg = g_Khi + hb;
    const __nv_bfloat16* Klg = g_Klo + hb;
    const __nv_bfloat16* Vhg = g_Vhi + hb;
    const __nv_bfloat16* Vlg = g_Vlo + hb;

    // ---- load Q tile (128x64 hi/lo) ----
#pragma unroll
    for (int it = 0; it < 4; ++it) {
        const int c = t + it * 256;
        const int row = c >> 3, col = (c & 7) * 8;
        *(uint4*)&fsm[row * KS + col]             = *(const uint4*)(Qh + row * DK + col);
        *(uint4*)&fsm[128 * KS + row * KS + col]  = *(const uint4*)(Ql + row * DK + col);
    }

    // ---- cp.async issue of one kv tile into stage st ----
    auto issue = [&](int kvi, int st) {
        const __nv_bfloat16* kh = Khg + (size_t)kvi * 64 * DK;
        const __nv_bfloat16* kl = Klg + (size_t)kvi * 64 * DK;
        const __nv_bfloat16* vh = Vhg + (size_t)kvi * 64 * DK;
        const __nv_bfloat16* vl = Vlg + (size_t)kvi * 64 * DK;
        const uint32_t sb = uStage0 + st * FSTG;
#pragma unroll
        for (int it = 0; it < 2; ++it) {
            const int c = t + it * 256;
            const int row = c >> 3, col = (c & 7) * 8;
            const uint32_t so = sb + (uint32_t)(row * KS + col) * 2;
            const size_t g = (size_t)row * DK + col;
            cp16(so,            kh + g);
            cp16(so + FARR,     kl + g);
            cp16(so + 2 * FARR, vh + g);
            cp16(so + 3 * FARR, vl + g);
        }
    };

    issue(0, 0);
    CP_COMMIT();
    __syncthreads();   // Q tile visible

    // ---- Q A-fragments (persistent) ----
    uint32_t qh[4][4], ql[4][4];
    const int aRow = w * 16 + (lane & 15);
    const int aCol = (lane >> 4) * 8;
#pragma unroll
    for (int ks = 0; ks < 4; ++ks) {
        const uint32_t off = (uint32_t)(aRow * KS + ks * 16 + aCol) * 2;
        ldm_x4(qh[ks], uQh + off);
        ldm_x4(ql[ks], uQl + off);
    }

    float o[8][4];
#pragma unroll
    for (int nt = 0; nt < 8; ++nt)
#pragma unroll
        for (int r = 0; r < 4; ++r) o[nt][r] = 0.f;
    float rm0 = -1e30f, rm1 = -1e30f, rl0 = 0.f, rl1 = 0.f;

    const int bRow = (lane & 7) + ((lane >> 4) << 3);       // K (non-trans B)
    const int bCol = ((lane >> 3) & 1) * 8;
    const int vRow = (lane & 7) + (((lane >> 3) & 1) << 3); // V (trans B)
    const int vCol = (lane >> 4) * 8;

    for (int kv = 0; kv < SEQ / 64; ++kv) {
        const int buf = kv & 1;
        const bool more = (kv + 1) < (SEQ / 64);
        if (more) { issue(kv + 1, buf ^ 1); CP_COMMIT(); CP_WAIT1(); }
        else      { CP_WAIT0(); }
        __syncthreads();

        const uint32_t uKh = uStage0 + buf * FSTG;
        const uint32_t uKl = uKh + FARR;
        const uint32_t uVh = uKh + 2 * FARR;
        const uint32_t uVl = uKh + 3 * FARR;

        // ---- S = Q K^T (bf16x3), ks-outer / nb-inner for ILP ----
        float s[8][4];
#pragma unroll
        for (int nt = 0; nt < 8; ++nt)
#pragma unroll
            for (int r = 0; r < 4; ++r) s[nt][r] = 0.f;

#pragma unroll
        for (int ks = 0; ks < 4; ++ks) {
#pragma unroll
            for (int nb = 0; nb < 4; ++nb) {
                const uint32_t off = (uint32_t)((nb * 16 + bRow) * KS + ks * 16 + bCol) * 2;
                uint32_t kbh[4], kbl[4];
                ldm_x4(kbh, uKh + off);
                ldm_x4(kbl, uKl + off);
                mma16816(s[nb * 2],     qh[ks], kbh);
                mma16816(s[nb * 2 + 1], qh[ks], kbh + 2);
                mma16816(s[nb * 2],     qh[ks], kbl);
                mma16816(s[nb * 2 + 1], qh[ks], kbl + 2);
                mma16816(s[nb * 2],     ql[ks], kbh);
                mma16816(s[nb * 2 + 1], ql[ks], kbh + 2);
            }
        }

        // ---- online softmax in log2 domain ----
        float mx0 = -1e30f, mx1 = -1e30f;
#pragma unroll
        for (int nt = 0; nt < 8; ++nt) {
            mx0 = fmaxf(mx0, fmaxf(s[nt][0], s[nt][1]));
            mx1 = fmaxf(mx1, fmaxf(s[nt][2], s[nt][3]));
        }
        mx0 = fmaxf(mx0, __shfl_xor_sync(0xffffffffu, mx0, 1));
        mx0 = fmaxf(mx0, __shfl_xor_sync(0xffffffffu, mx0, 2));
        mx1 = fmaxf(mx1, __shfl_xor_sync(0xffffffffu, mx1, 1));
        mx1 = fmaxf(mx1, __shfl_xor_sync(0xffffffffu, mx1, 2));
        const float nm0 = fmaxf(rm0, mx0), nm1 = fmaxf(rm1, mx1);
        const float sc0 = exp2f(rm0 - nm0), sc1 = exp2f(rm1 - nm1);
        rm0 = nm0; rm1 = nm1;

        float ls0 = 0.f, ls1 = 0.f;
#pragma unroll
        for (int nt = 0; nt < 8; ++nt) {
            s[nt][0] = exp2f(s[nt][0] - nm0);
            s[nt][1] = exp2f(s[nt][1] - nm0);
            s[nt][2] = exp2f(s[nt][2] - nm1);
            s[nt][3] = exp2f(s[nt][3] - nm1);
            ls0 += s[nt][0] + s[nt][1];
            ls1 += s[nt][2] + s[nt][3];
        }
        ls0 += __shfl_xor_sync(0xffffffffu, ls0, 1);
        ls0 += __shfl_xor_sync(0xffffffffu, ls0, 2);
        ls1 += __shfl_xor_sync(0xffffffffu, ls1, 1);
        ls1 += __shfl_xor_sync(0xffffffffu, ls1, 2);
        rl0 = rl0 * sc0 + ls0;
        rl1 = rl1 * sc1 + ls1;

#pragma unroll
        for (int nt = 0; nt < 8; ++nt) {
            o[nt][0] *= sc0; o[nt][1] *= sc0;
            o[nt][2] *= sc1; o[nt][3] *= sc1;
        }

        // ---- pack P hi/lo (S c-frag == P a-frag layout) ----
        uint32_t ph[4][4], pl[4][4];
#pragma unroll
        for (int j = 0; j < 4; ++j) {
            const float* p0 = s[2 * j];
            const float* p1 = s[2 * j + 1];
            ph[j][0] = packbf(p0[0], p0[1]);
            ph[j][1] = packbf(p0[2], p0[3]);
            ph[j][2] = packbf(p1[0], p1[1]);
            ph[j][3] = packbf(p1[2], p1[3]);
            float r00 = p0[0] - __bfloat162float(__float2bfloat16(p0[0]));
            float r01 = p0[1] - __bfloat162float(__float2bfloat16(p0[1]));
            float r02 = p0[2] - __bfloat162float(__float2bfloat16(p0[2]));
            float r03 = p0[3] - __bfloat162float(__float2bfloat16(p0[3]));
            float r10 = p1[0] - __bfloat162float(__float2bfloat16(p1[0]));
            float r11 = p1[1] - __bfloat162float(__float2bfloat16(p1[1]));
            float r12 = p1[2] - __bfloat162float(__float2bfloat16(p1[2]));
            float r13 = p1[3] - __bfloat162float(__float2bfloat16(p1[3]));
            pl[j][0] = packbf(r00, r01);
            pl[j][1] = packbf(r02, r03);
            pl[j][2] = packbf(r10, r11);
            pl[j][3] = packbf(r12, r13);
        }

        // ---- O += P V (bf16x3, V via ldmatrix.trans), ks-outer / nb-inner ----
#pragma unroll
        for (int ks = 0; ks < 4; ++ks) {
#pragma unroll
            for (int nb = 0; nb < 4; ++nb) {
                const uint32_t off = (uint32_t)((ks * 16 + vRow) * KS + nb * 16 + vCol) * 2;
                uint32_t vbh[4], vbl[4];
                ldm_x4t(vbh, uVh + off);
                ldm_x4t(vbl, uVl + off);
                mma16816(o[nb * 2],     ph[ks], vbh);
                mma16816(o[nb * 2 + 1], ph[ks], vbh + 2);
                mma16816(o[nb * 2],     ph[ks], vbl);
                mma16816(o[nb * 2 + 1], ph[ks], vbl + 2);
                mma16816(o[nb * 2],     pl[ks], vbh);
                mma16816(o[nb * 2 + 1], pl[ks], vbh + 2);
            }
        }
        __syncthreads();
    }

    // ---- epilogue: normalize, write O hi/lo bf16 into g_Ahi/g_Alo ----
    const float inv0 = 1.f / rl0, inv1 = 1.f / rl1;
    const int row0 = qb + w * 16 + (lane >> 2);
    const int cbase = h * DK + 2 * (lane & 3);
    const size_t ob0 = ((size_t)b * SEQ + row0) * DMODEL;
    const size_t ob1 = ob0 + 8 * DMODEL;
#pragma unroll
    for (int nt = 0; nt < 8; ++nt) {
        float v0x = o[nt][0] * inv0, v0y = o[nt][1] * inv0;
        float v1x = o[nt][2] * inv1, v1y = o[nt][3] * inv1;
        const size_t c0 = ob0 + cbase + nt * 8;
        const size_t c1 = ob1 + cbase + nt * 8;
        *(uint32_t*)(g_Ahi + c0) = packbf(v0x, v0y);
        *(uint32_t*)(g_Ahi + c1) = packbf(v1x, v1y);
        float l0x = v0x - __bfloat162float(__float2bfloat16(v0x));
        float l0y = v0y - __bfloat162float(__float2bfloat16(v0y));
        float l1x = v1x - __bfloat162float(__float2bfloat16(v1x));
        float l1y = v1y - __bfloat162float(__float2bfloat16(v1y));
        *(uint32_t*)(g_Alo + c0) = packbf(l0x, l0y);
        *(uint32_t*)(g_Alo + c1) = packbf(l1x, l1y);
    }
}

// ---------------------------------------------------------------------------
// Launch
// ---------------------------------------------------------------------------
extern "C" void kernel_launch(void* const* d_in, const int* in_sizes, int n_in,
                              void* d_out, int out_size)
{
    const float* q  = (const float*)d_in[0];
    const float* k  = (const float*)d_in[1];
    const float* v  = (const float*)d_in[2];
    const float* Wq = (const float*)d_in[3];
    const float* bq = (const float*)d_in[4];
    const float* Wk = (const float*)d_in[5];
    const float* bk = (const float*)d_in[6];
    const float* Wv = (const float*)d_in[7];
    const float* bv = (const float*)d_in[8];
    const float* Wo = (const float*)d_in[9];
    const float* bo = (const float*)d_in[10];
    float* out = (float*)d_out;

    __nv_bfloat16 *pAhi, *pAlo, *pWhi, *pWlo;
    __nv_bfloat16 *pQh, *pQl, *pKh, *pKl, *pVh, *pVl;
    cudaGetSymbolAddress((void**)&pAhi, g_Ahi);
    cudaGetSymbolAddress((void**)&pAlo, g_Alo);
    cudaGetSymbolAddress((void**)&pWhi, g_Whi);
    cudaGetSymbolAddress((void**)&pWlo, g_Wlo);
    cudaGetSymbolAddress((void**)&pQh, g_Qhi);
    cudaGetSymbolAddress((void**)&pQl, g_Qlo);
    cudaGetSymbolAddress((void**)&pKh, g_Khi);
    cudaGetSymbolAddress((void**)&pKl, g_Klo);
    cudaGetSymbolAddress((void**)&pVh, g_Vhi);
    cudaGetSymbolAddress((void**)&pVl, g_Vlo);

    cudaFuncSetAttribute(gemm_mma, cudaFuncAttributeMaxDynamicSharedMemorySize, GEMM_SMEM);
    cudaFuncSetAttribute(flash_mma, cudaFuncAttributeMaxDynamicSharedMemorySize, FLASH_SMEM);

    const dim3 ggrid(DMODEL / BN, MROWS / BM);   // (4, 64)

    // QKV projections -> bf16 hi/lo.
    // Q scale = (1/sqrt(dk)) * log2(e): scores come out in the log2 domain.
    auto proj = [&](const float* act, const float* W, const float* bias,
                    __nv_bfloat16* hi, __nv_bfloat16* lo, float scale) {
        split_kernel<<<1024, 256>>>(act, pAhi, pAlo, MROWS * DMODEL);
        split_kernel<<<256, 256>>>(W, pWhi, pWlo, DMODEL * DMODEL);
        gemm_mma<<<ggrid, 256, GEMM_SMEM>>>(pAhi, pAlo, pWhi, pWlo, bias,
                                            nullptr, hi, lo, scale, 0);
    };

    proj(q, Wq, bq, pQh, pQl, 0.125f * 1.4426950408889634f);
    proj(k, Wk, bk, pKh, pKl, 1.0f);
    proj(v, Wv, bv, pVh, pVl, 1.0f);

    const dim3 fgrid(SEQ / 128, HEADS, BATCH);   // (16, 16, 4)
    flash_mma<<<fgrid, 256, FLASH_SMEM>>>();     // writes O hi/lo to g_Ahi/g_Alo

    // output projection (reads O hi/lo directly; fp32 result)
    split_kernel<<<256, 256>>>(Wo, pWhi, pWlo, DMODEL * DMODEL);
    gemm_mma<<<ggrid, 256, GEMM_SMEM>>>(pAhi, pAlo, pWhi, pWlo, bo,
                                        out, nullptr, nullptr, 1.0f, 1);
}

// round 17
// speedup vs baseline: 3.3481x; 1.0036x over previous
#include <cuda_runtime.h>
#include <cuda_bf16.h>
#include <cstdint>

// ---------------------------------------------------------------------------
// MultiHeadAttention: B=4, H=16, S=2048, D=1024, dk=64, fp32.
// All matmul on HMMA bf16x3 split (base ISA; tcgen05 rejected by compute_103).
// R17 (= R16 resubmit after broker flake): product-outer mma ordering
// (acc revisit distance 8) in GEMM + flash; fused launches (1 act-split,
// 1 weight-split, 1 z-indexed QKV GEMM).
// ---------------------------------------------------------------------------

#define BATCH 4
#define HEADS 16
#define SEQ   2048
#define DMODEL 1024
#define DK    64
#define MROWS (BATCH * SEQ)        // 8192

// ---------------- scratch (__device__ globals; no allocation allowed) -------
__device__ __nv_bfloat16 g_Qhi[BATCH * HEADS * SEQ * DK];
__device__ __nv_bfloat16 g_Qlo[BATCH * HEADS * SEQ * DK];
__device__ __nv_bfloat16 g_Khi[BATCH * HEADS * SEQ * DK];
__device__ __nv_bfloat16 g_Klo[BATCH * HEADS * SEQ * DK];
__device__ __nv_bfloat16 g_Vhi[BATCH * HEADS * SEQ * DK];
__device__ __nv_bfloat16 g_Vlo[BATCH * HEADS * SEQ * DK];

__device__ __nv_bfloat16 g_A1hi[MROWS * DMODEL];   // q act; later O from flash
__device__ __nv_bfloat16 g_A1lo[MROWS * DMODEL];
__device__ __nv_bfloat16 g_A2hi[MROWS * DMODEL];   // k act
__device__ __nv_bfloat16 g_A2lo[MROWS * DMODEL];
__device__ __nv_bfloat16 g_A3hi[MROWS * DMODEL];   // v act
__device__ __nv_bfloat16 g_A3lo[MROWS * DMODEL];
__device__ __nv_bfloat16 g_Whi[4 * DMODEL * DMODEL];  // Wq,Wk,Wv,Wo
__device__ __nv_bfloat16 g_Wlo[4 * DMODEL * DMODEL];

// ---------------- helpers (base ISA) ----------------------------------------
__device__ __forceinline__ uint32_t smem_u32(const void* p) {
    uint32_t a;
    asm("{ .reg .u64 t; cvta.to.shared.u64 t, %1; cvt.u32.u64 %0, t; }" : "=r"(a) : "l"(p));
    return a;
}
__device__ __forceinline__ void ldm_x4(uint32_t* r, uint32_t addr) {
    asm volatile("ldmatrix.sync.aligned.m8n8.x4.shared.b16 {%0,%1,%2,%3}, [%4];"
                 : "=r"(r[0]), "=r"(r[1]), "=r"(r[2]), "=r"(r[3]) : "r"(addr));
}
__device__ __forceinline__ void ldm_x4t(uint32_t* r, uint32_t addr) {
    asm volatile("ldmatrix.sync.aligned.m8n8.x4.trans.shared.b16 {%0,%1,%2,%3}, [%4];"
                 : "=r"(r[0]), "=r"(r[1]), "=r"(r[2]), "=r"(r[3]) : "r"(addr));
}
__device__ __forceinline__ void mma16816(float* c, const uint32_t* a, const uint32_t* b) {
    asm volatile("mma.sync.aligned.m16n8k16.row.col.f32.bf16.bf16.f32 "
                 "{%0,%1,%2,%3}, {%4,%5,%6,%7}, {%8,%9}, {%0,%1,%2,%3};"
                 : "+f"(c[0]), "+f"(c[1]), "+f"(c[2]), "+f"(c[3])
                 : "r"(a[0]), "r"(a[1]), "r"(a[2]), "r"(a[3]), "r"(b[0]), "r"(b[1]));
}
__device__ __forceinline__ uint32_t packbf(float a, float b) {
    __nv_bfloat162 r = __floats2bfloat162_rn(a, b);
    return *(uint32_t*)&r;
}
__device__ __forceinline__ void cp16(uint32_t saddr, const void* g) {
    asm volatile("cp.async.cg.shared.global [%0], [%1], 16;" :: "r"(saddr), "l"(g));
}
#define CP_COMMIT() asm volatile("cp.async.commit_group;")
#define CP_WAIT1()  asm volatile("cp.async.wait_group 1;")
#define CP_WAIT0()  asm volatile("cp.async.wait_group 0;")

// ---------------------------------------------------------------------------
// Split kernels: fp32 -> (bf16 hi, bf16 lo)
// ---------------------------------------------------------------------------
__device__ __forceinline__ void split_body(const float* __restrict__ x,
                                           __nv_bfloat16* __restrict__ hi,
                                           __nv_bfloat16* __restrict__ lo, int n)
{
    int i = (blockIdx.x * blockDim.x + threadIdx.x) * 4;
    const int stride = gridDim.x * blockDim.x * 4;
    for (; i < n; i += stride) {
        float4 v = *(const float4*)(x + i);
        __nv_bfloat16 h0 = __float2bfloat16(v.x);
        __nv_bfloat16 h1 = __float2bfloat16(v.y);
        __nv_bfloat16 h2 = __float2bfloat16(v.z);
        __nv_bfloat16 h3 = __float2bfloat16(v.w);
        __nv_bfloat16 l0 = __float2bfloat16(v.x - __bfloat162float(h0));
        __nv_bfloat16 l1 = __float2bfloat16(v.y - __bfloat162float(h1));
        __nv_bfloat16 l2 = __float2bfloat16(v.z - __bfloat162float(h2));
        __nv_bfloat16 l3 = __float2bfloat16(v.w - __bfloat162float(h3));
        *(__nv_bfloat162*)(hi + i)     = __nv_bfloat162(h0, h1);
        *(__nv_bfloat162*)(hi + i + 2) = __nv_bfloat162(h2, h3);
        *(__nv_bfloat162*)(lo + i)     = __nv_bfloat162(l0, l1);
        *(__nv_bfloat162*)(lo + i + 2) = __nv_bfloat162(l2, l3);
    }
}

__global__ void __launch_bounds__(256)
split3_act(const float* __restrict__ s0, const float* __restrict__ s1,
           const float* __restrict__ s2,
           __nv_bfloat16* __restrict__ h0, __nv_bfloat16* __restrict__ l0,
           __nv_bfloat16* __restrict__ h1, __nv_bfloat16* __restrict__ l1,
           __nv_bfloat16* __restrict__ h2, __nv_bfloat16* __restrict__ l2, int n)
{
    const int sel = blockIdx.y;
    const float* x = (sel == 0) ? s0 : (sel == 1) ? s1 : s2;
    __nv_bfloat16* hi = (sel == 0) ? h0 : (sel == 1) ? h1 : h2;
    __nv_bfloat16* lo = (sel == 0) ? l0 : (sel == 1) ? l1 : l2;
    split_body(x, hi, lo, n);
}

__global__ void __launch_bounds__(256)
split4_w(const float* __restrict__ w0, const float* __restrict__ w1,
         const float* __restrict__ w2, const float* __restrict__ w3,
         __nv_bfloat16* __restrict__ hi, __nv_bfloat16* __restrict__ lo, int n)
{
    const int sel = blockIdx.y;
    const float* x = (sel == 0) ? w0 : (sel == 1) ? w1 : (sel == 2) ? w2 : w3;
    split_body(x, hi + (size_t)sel * n, lo + (size_t)sel * n, n);
}

// ---------------------------------------------------------------------------
// HMMA GEMM body, cp.async double-buffered: C = A*B^T + bias, bf16x3 split.
// Block tile 128(M) x 256(N), K-tile 32, 8 warps (2m x 4n), warp tile 64x64.
// Product-outer mma ordering: acc revisit distance = 8 mmas.
// mode 0: v=(acc+bias)*scale -> bf16 hi/lo scatter [b][h][s][dk]
// mode 1: fp32 row-major [M,N]
// ---------------------------------------------------------------------------
#define BM 128
#define BN 256
#define BK 32
#define SROW 40
#define GMATA (BM * SROW * 2)
#define GMATB (BN * SROW * 2)
#define GSTG  (2 * GMATA + 2 * GMATB)
#define GEMM_SMEM (2 * GSTG)           // 122880 B

__device__ __forceinline__ void gemm_body(
    const __nv_bfloat16* __restrict__ Ahi, const __nv_bfloat16* __restrict__ Alo,
    const __nv_bfloat16* __restrict__ Bhi, const __nv_bfloat16* __restrict__ Blo,
    const float* __restrict__ bias, float* __restrict__ C,
    __nv_bfloat16* __restrict__ Chi, __nv_bfloat16* __restrict__ Clo,
    float scale, int mode)
{
    extern __shared__ __nv_bfloat16 gsm[];
    const uint32_t uS = smem_u32(gsm);

    const int t = threadIdx.x;
    const int w = t >> 5, lane = t & 31;
    const int bm = blockIdx.y * BM;
    const int bn = blockIdx.x * BN;
    const int wm = (w >> 2) * 64;
    const int wn = (w & 3) * 64;

    float acc[4][8][4];
#pragma unroll
    for (int mi = 0; mi < 4; ++mi)
#pragma unroll
        for (int ni = 0; ni < 8; ++ni)
#pragma unroll
            for (int r = 0; r < 4; ++r) acc[mi][ni][r] = 0.f;

    const int aRow = wm + (lane & 15);
    const int aCol = (lane >> 4) * 8;
    const int bRowN = wn + (lane & 7) + ((lane >> 4) << 3);
    const int bColK = ((lane >> 3) & 1) * 8;

    auto issue = [&](int kt, int st) {
        const int kbase = kt * BK;
        const uint32_t sb = uS + st * GSTG;
#pragma unroll
        for (int it = 0; it < 2; ++it) {
            const int c = t + it * 256;
            const int row = c >> 2;
            const int col = (c & 3) * 8;
            const uint32_t so = sb + (uint32_t)(row * SROW + col) * 2;
            const size_t gA = (size_t)(bm + row) * DMODEL + kbase + col;
            cp16(so,         Ahi + gA);
            cp16(so + GMATA, Alo + gA);
        }
#pragma unroll
        for (int it = 0; it < 4; ++it) {
            const int c = t + it * 256;
            const int row = c >> 2;
            const int col = (c & 3) * 8;
            const uint32_t so = sb + 2 * GMATA + (uint32_t)(row * SROW + col) * 2;
            const size_t gB = (size_t)(bn + row) * DMODEL + kbase + col;
            cp16(so,         Bhi + gB);
            cp16(so + GMATB, Blo + gB);
        }
    };

    issue(0, 0);
    CP_COMMIT();

    for (int kt = 0; kt < DMODEL / BK; ++kt) {
        const int buf = kt & 1;
        const bool more = (kt + 1) < (DMODEL / BK);
        if (more) { issue(kt + 1, buf ^ 1); CP_COMMIT(); CP_WAIT1(); }
        else      { CP_WAIT0(); }
        __syncthreads();

        const uint32_t uAhi = uS + buf * GSTG;
        const uint32_t uAlo = uAhi + GMATA;
        const uint32_t uBhi = uAhi + 2 * GMATA;
        const uint32_t uBlo = uBhi + GMATB;

#pragma unroll
        for (int ks = 0; ks < 2; ++ks) {
            const int k0 = ks * 16;
            uint32_t bhi[8][2], blo[8][2];
#pragma unroll
            for (int nb = 0; nb < 4; ++nb) {
                uint32_t r[4];
                const uint32_t off = (uint32_t)((bRowN + nb * 16) * SROW + k0 + bColK) * 2;
                ldm_x4(r, uBhi + off);
                bhi[nb * 2 + 0][0] = r[0]; bhi[nb * 2 + 0][1] = r[1];
                bhi[nb * 2 + 1][0] = r[2]; bhi[nb * 2 + 1][1] = r[3];
                ldm_x4(r, uBlo + off);
                blo[nb * 2 + 0][0] = r[0]; blo[nb * 2 + 0][1] = r[1];
                blo[nb * 2 + 1][0] = r[2]; blo[nb * 2 + 1][1] = r[3];
            }
#pragma unroll
            for (int mi = 0; mi < 4; ++mi) {
                uint32_t ahi[4], alo[4];
                const uint32_t off = (uint32_t)((aRow + mi * 16) * SROW + k0 + aCol) * 2;
                ldm_x4(ahi, uAhi + off);
                ldm_x4(alo, uAlo + off);
                // product-outer: each acc revisited 8 mmas apart
#pragma unroll
                for (int ni = 0; ni < 8; ++ni) mma16816(acc[mi][ni], ahi, bhi[ni]);
#pragma unroll
                for (int ni = 0; ni < 8; ++ni) mma16816(acc[mi][ni], ahi, blo[ni]);
#pragma unroll
                for (int ni = 0; ni < 8; ++ni) mma16816(acc[mi][ni], alo, bhi[ni]);
            }
        }
        __syncthreads();
    }

    // ---- epilogue ----
    const int r0 = lane >> 2;
    const int cp = (lane & 3) * 2;
#pragma unroll
    for (int mi = 0; mi < 4; ++mi) {
#pragma unroll
        for (int ni = 0; ni < 8; ++ni) {
            const int n = bn + wn + ni * 8 + cp;
            const float2 b2 = *(const float2*)(bias + n);
#pragma unroll
            for (int half = 0; half < 2; ++half) {
                const int m = bm + wm + mi * 16 + r0 + half * 8;
                float vx = (acc[mi][ni][half * 2 + 0] + b2.x) * scale;
                float vy = (acc[mi][ni][half * 2 + 1] + b2.y) * scale;
                if (mode == 0) {
                    const int bb = m >> 11, s = m & 2047;
                    const int h = n >> 6, dd = n & 63;
                    const size_t off = (((size_t)(bb * HEADS + h) * SEQ + s) << 6) + dd;
                    __nv_bfloat16 hx = __float2bfloat16(vx);
                    __nv_bfloat16 hy = __float2bfloat16(vy);
                    *(uint32_t*)(Chi + off) = packbf(vx, vy);
                    *(uint32_t*)(Clo + off) = packbf(vx - __bfloat162float(hx),
                                                     vy - __bfloat162float(hy));
                } else {
                    float2 v; v.x = vx; v.y = vy;
                    *(float2*)(C + (size_t)m * DMODEL + n) = v;
                }
            }
        }
    }
}

// out-projection (mode 1)
__global__ void __launch_bounds__(256, 1)
gemm_mma(const __nv_bfloat16* __restrict__ Ahi, const __nv_bfloat16* __restrict__ Alo,
         const __nv_bfloat16* __restrict__ Bhi, const __nv_bfloat16* __restrict__ Blo,
         const float* __restrict__ bias, float* __restrict__ C)
{
    gemm_body(Ahi, Alo, Bhi, Blo, bias, C, nullptr, nullptr, 1.0f, 1);
}

// fused QKV projections: blockIdx.z selects {q,k,v}
__global__ void __launch_bounds__(256, 1)
gemm_qkv(const __nv_bfloat16* __restrict__ A1hi, const __nv_bfloat16* __restrict__ A1lo,
         const __nv_bfloat16* __restrict__ A2hi, const __nv_bfloat16* __restrict__ A2lo,
         const __nv_bfloat16* __restrict__ A3hi, const __nv_bfloat16* __restrict__ A3lo,
         const __nv_bfloat16* __restrict__ Whi, const __nv_bfloat16* __restrict__ Wlo,
         const float* __restrict__ b0, const float* __restrict__ b1,
         const float* __restrict__ b2,
         __nv_bfloat16* __restrict__ Qh, __nv_bfloat16* __restrict__ Ql,
         __nv_bfloat16* __restrict__ Kh, __nv_bfloat16* __restrict__ Kl,
         __nv_bfloat16* __restrict__ Vh, __nv_bfloat16* __restrict__ Vl,
         float qscale)
{
    const int z = blockIdx.z;
    const __nv_bfloat16* Ahi = (z == 0) ? A1hi : (z == 1) ? A2hi : A3hi;
    const __nv_bfloat16* Alo = (z == 0) ? A1lo : (z == 1) ? A2lo : A3lo;
    const __nv_bfloat16* Bhi = Whi + (size_t)z * DMODEL * DMODEL;
    const __nv_bfloat16* Blo = Wlo + (size_t)z * DMODEL * DMODEL;
    const float* bias = (z == 0) ? b0 : (z == 1) ? b1 : b2;
    __nv_bfloat16* Chi = (z == 0) ? Qh : (z == 1) ? Kh : Vh;
    __nv_bfloat16* Clo = (z == 0) ? Ql : (z == 1) ? Kl : Vl;
    const float scale = (z == 0) ? qscale : 1.0f;
    gemm_body(Ahi, Alo, Bhi, Blo, bias, nullptr, Chi, Clo, scale, 0);
}

// ---------------------------------------------------------------------------
// Flash attention via HMMA bf16x3, cp.async double-buffered K/V,
// ldmatrix.trans for V. Block = 256 threads (8 warps), q-tile 128, kv-tile 64.
// Log2-domain softmax (log2e folded into Q). Product-outer mma ordering:
// B fragments for a k-slice preloaded, acc revisit distance = 8 mmas.
// Epilogue writes O hi/lo bf16 into g_A1hi/g_A1lo.
// ---------------------------------------------------------------------------
#define KS 72
#define FARR   (64 * KS * 2)
#define FQARR  (128 * KS * 2)
#define FSTG   (4 * FARR)
#define FLASH_SMEM (2 * FQARR + 2 * FSTG)      // 110592 B

__global__ void __launch_bounds__(256)
flash_mma()
{
    extern __shared__ __nv_bfloat16 fsm[];
    const uint32_t uS = smem_u32(fsm);
    const uint32_t uQh = uS, uQl = uS + FQARR;
    const uint32_t uStage0 = uS + 2 * FQARR;

    const int t = threadIdx.x, w = t >> 5, lane = t & 31;
    const int b = blockIdx.z, h = blockIdx.y, qb = blockIdx.x * 128;
    const size_t hb = (size_t)(b * HEADS + h) * SEQ * DK;

    const __nv_bfloat16* Qh = g_Qhi + hb + (size_t)qb * DK;
    const __nv_bfloat16* Ql = g_Qlo + hb + (size_t)qb * DK;
    const __nv_bfloat16* Khg = g_Khi + hb;
    const __nv_bfloat16* Klg = g_Klo + hb;
    const __nv_bfloat16* Vhg = g_Vhi + hb;
    const __nv_bfloat16* Vlg = g_Vlo + hb;

    // ---- load Q tile (128x64 hi/lo) ----
#pragma unroll
    for (int it = 0; it < 4; ++it) {
        const int c = t + it * 256;
        const int row = c >> 3, col = (c & 7) * 8;
        *(uint4*)&fsm[row * KS + col]             = *(const uint4*)(Qh + row * DK + col);
        *(uint4*)&fsm[128 * KS + row * KS + col]  = *(const uint4*)(Ql + row * DK + col);
    }

    auto issue = [&](int kvi, int st) {
        const __nv_bfloat16* kh = Khg + (size_t)kvi * 64 * DK;
        const __nv_bfloat16* kl = Klg + (size_t)kvi * 64 * DK;
        const __nv_bfloat16* vh = Vhg + (size_t)kvi * 64 * DK;
        const __nv_bfloat16* vl = Vlg + (size_t)kvi * 64 * DK;
        const uint32_t sb = uStage0 + st * FSTG;
#pragma unroll
        for (int it = 0; it < 2; ++it) {
            const int c = t + it * 256;
            const int row = c >> 3, col = (c & 7) * 8;
            const uint32_t so = sb + (uint32_t)(row * KS + col) * 2;
            const size_t g = (size_t)row * DK + col;
            cp16(so,            kh + g);
            cp16(so + FARR,     kl + g);
            cp16(so + 2 * FARR, vh + g);
            cp16(so + 3 * FARR, vl + g);
        }
    };

    issue(0, 0);
    CP_COMMIT();
    __syncthreads();   // Q tile visible

    // ---- Q A-fragments (persistent) ----
    uint32_t qh[4][4], ql[4][4];
    const int aRow = w * 16 + (lane & 15);
    const int aCol = (lane >> 4) * 8;
#pragma unroll
    for (int ks = 0; ks < 4; ++ks) {
        const uint32_t off = (uint32_t)(aRow * KS + ks * 16 + aCol) * 2;
        ldm_x4(qh[ks], uQh + off);
        ldm_x4(ql[ks], uQl + off);
    }

    float o[8][4];
#pragma unroll
    for (int nt = 0; nt < 8; ++nt)
#pragma unroll
        for (int r = 0; r < 4; ++r) o[nt][r] = 0.f;
    float rm0 = -1e30f, rm1 = -1e30f, rl0 = 0.f, rl1 = 0.f;

    const int bRow = (lane & 7) + ((lane >> 4) << 3);       // K (non-trans B)
    const int bCol = ((lane >> 3) & 1) * 8;
    const int vRow = (lane & 7) + (((lane >> 3) & 1) << 3); // V (trans B)
    const int vCol = (lane >> 4) * 8;

    for (int kv = 0; kv < SEQ / 64; ++kv) {
        const int buf = kv & 1;
        const bool more = (kv + 1) < (SEQ / 64);
        if (more) { issue(kv + 1, buf ^ 1); CP_COMMIT(); CP_WAIT1(); }
        else      { CP_WAIT0(); }
        __syncthreads();

        const uint32_t uKh = uStage0 + buf * FSTG;
        const uint32_t uKl = uKh + FARR;
        const uint32_t uVh = uKh + 2 * FARR;
        const uint32_t uVl = uKh + 3 * FARR;

        // ---- S = Q K^T (bf16x3), fragments preloaded per k-slice ----
        float s[8][4];
#pragma unroll
        for (int nt = 0; nt < 8; ++nt)
#pragma unroll
            for (int r = 0; r < 4; ++r) s[nt][r] = 0.f;

#pragma unroll
        for (int ks = 0; ks < 4; ++ks) {
            uint32_t kbh[4][4], kbl[4][4];
#pragma unroll
            for (int nb = 0; nb < 4; ++nb) {
                const uint32_t off = (uint32_t)((nb * 16 + bRow) * KS + ks * 16 + bCol) * 2;
                ldm_x4(kbh[nb], uKh + off);
                ldm_x4(kbl[nb], uKl + off);
            }
#pragma unroll
            for (int nb = 0; nb < 4; ++nb) {
                mma16816(s[nb * 2],     qh[ks], kbh[nb]);
                mma16816(s[nb * 2 + 1], qh[ks], kbh[nb] + 2);
            }
#pragma unroll
            for (int nb = 0; nb < 4; ++nb) {
                mma16816(s[nb * 2],     qh[ks], kbl[nb]);
                mma16816(s[nb * 2 + 1], qh[ks], kbl[nb] + 2);
            }
#pragma unroll
            for (int nb = 0; nb < 4; ++nb) {
                mma16816(s[nb * 2],     ql[ks], kbh[nb]);
                mma16816(s[nb * 2 + 1], ql[ks], kbh[nb] + 2);
            }
        }

        // ---- online softmax in log2 domain ----
        float mx0 = -1e30f, mx1 = -1e30f;
#pragma unroll
        for (int nt = 0; nt < 8; ++nt) {
            mx0 = fmaxf(mx0, fmaxf(s[nt][0], s[nt][1]));
            mx1 = fmaxf(mx1, fmaxf(s[nt][2], s[nt][3]));
        }
        mx0 = fmaxf(mx0, __shfl_xor_sync(0xffffffffu, mx0, 1));
        mx0 = fmaxf(mx0, __shfl_xor_sync(0xffffffffu, mx0, 2));
        mx1 = fmaxf(mx1, __shfl_xor_sync(0xffffffffu, mx1, 1));
        mx1 = fmaxf(mx1, __shfl_xor_sync(0xffffffffu, mx1, 2));
        const float nm0 = fmaxf(rm0, mx0), nm1 = fmaxf(rm1, mx1);
        const float sc0 = exp2f(rm0 - nm0), sc1 = exp2f(rm1 - nm1);
        rm0 = nm0; rm1 = nm1;

        float ls0 = 0.f, ls1 = 0.f;
#pragma unroll
        for (int nt = 0; nt < 8; ++nt) {
            s[nt][0] = exp2f(s[nt][0] - nm0);
            s[nt][1] = exp2f(s[nt][1] - nm0);
            s[nt][2] = exp2f(s[nt][2] - nm1);
            s[nt][3] = exp2f(s[nt][3] - nm1);
            ls0 += s[nt][0] + s[nt][1];
            ls1 += s[nt][2] + s[nt][3];
        }
        ls0 += __shfl_xor_sync(0xffffffffu, ls0, 1);
        ls0 += __shfl_xor_sync(0xffffffffu, ls0, 2);
        ls1 += __shfl_xor_sync(0xffffffffu, ls1, 1);
        ls1 += __shfl_xor_sync(0xffffffffu, ls1, 2);
        rl0 = rl0 * sc0 + ls0;
        rl1 = rl1 * sc1 + ls1;

#pragma unroll
        for (int nt = 0; nt < 8; ++nt) {
            o[nt][0] *= sc0; o[nt][1] *= sc0;
            o[nt][2] *= sc1; o[nt][3] *= sc1;
        }

        // ---- pack P hi/lo (S c-frag == P a-frag layout) ----
        uint32_t ph[4][4], pl[4][4];
#pragma unroll
        for (int j = 0; j < 4; ++j) {
            const float* p0 = s[2 * j];
            const float* p1 = s[2 * j + 1];
            ph[j][0] = packbf(p0[0], p0[1]);
            ph[j][1] = packbf(p0[2], p0[3]);
            ph[j][2] = packbf(p1[0], p1[1]);
            ph[j][3] = packbf(p1[2], p1[3]);
            float r00 = p0[0] - __bfloat162float(__float2bfloat16(p0[0]));
            float r01 = p0[1] - __bfloat162float(__float2bfloat16(p0[1]));
            float r02 = p0[2] - __bfloat162float(__float2bfloat16(p0[2]));
            float r03 = p0[3] - __bfloat162float(__float2bfloat16(p0[3]));
            float r10 = p1[0] - __bfloat162float(__float2bfloat16(p1[0]));
            float r11 = p1[1] - __bfloat162float(__float2bfloat16(p1[1]));
            float r12 = p1[2] - __bfloat162float(__float2bfloat16(p1[2]));
            float r13 = p1[3] - __bfloat162float(__float2bfloat16(p1[3]));
            pl[j][0] = packbf(r00, r01);
            pl[j][1] = packbf(r02, r03);
            pl[j][2] = packbf(r10, r11);
            pl[j][3] = packbf(r12, r13);
        }

        // ---- O += P V (bf16x3, V via ldmatrix.trans), fragments preloaded ----
#pragma unroll
        for (int ks = 0; ks < 4; ++ks) {
            uint32_t vbh[4][4], vbl[4][4];
#pragma unroll
            for (int nb = 0; nb < 4; ++nb) {
                const uint32_t off = (uint32_t)((ks * 16 + vRow) * KS + nb * 16 + vCol) * 2;
                ldm_x4t(vbh[nb], uVh + off);
                ldm_x4t(vbl[nb], uVl + off);
            }
#pragma unroll
            for (int nb = 0; nb < 4; ++nb) {
                mma16816(o[nb * 2],     ph[ks], vbh[nb]);
                mma16816(o[nb * 2 + 1], ph[ks], vbh[nb] + 2);
            }
#pragma unroll
            for (int nb = 0; nb < 4; ++nb) {
                mma16816(o[nb * 2],     ph[ks], vbl[nb]);
                mma16816(o[nb * 2 + 1], ph[ks], vbl[nb] + 2);
            }
#pragma unroll
            for (int nb = 0; nb < 4; ++nb) {
                mma16816(o[nb * 2],     pl[ks], vbh[nb]);
                mma16816(o[nb * 2 + 1], pl[ks], vbh[nb] + 2);
            }
        }
        __syncthreads();
    }

    // ---- epilogue: normalize, write O hi/lo bf16 into g_A1hi/g_A1lo ----
    const float inv0 = 1.f / rl0, inv1 = 1.f / rl1;
    const int row0 = qb + w * 16 + (lane >> 2);
    const int cbase = h * DK + 2 * (lane & 3);
    const size_t ob0 = ((size_t)b * SEQ + row0) * DMODEL;
    const size_t ob1 = ob0 + 8 * DMODEL;
#pragma unroll
    for (int nt = 0; nt < 8; ++nt) {
        float v0x = o[nt][0] * inv0, v0y = o[nt][1] * inv0;
        float v1x = o[nt][2] * inv1, v1y = o[nt][3] * inv1;
        const size_t c0 = ob0 + cbase + nt * 8;
        const size_t c1 = ob1 + cbase + nt * 8;
        *(uint32_t*)(g_A1hi + c0) = packbf(v0x, v0y);
        *(uint32_t*)(g_A1hi + c1) = packbf(v1x, v1y);
        float l0x = v0x - __bfloat162float(__float2bfloat16(v0x));
        float l0y = v0y - __bfloat162float(__float2bfloat16(v0y));
        float l1x = v1x - __bfloat162float(__float2bfloat16(v1x));
        float l1y = v1y - __bfloat162float(__float2bfloat16(v1y));
        *(uint32_t*)(g_A1lo + c0) = packbf(l0x, l0y);
        *(uint32_t*)(g_A1lo + c1) = packbf(l1x, l1y);
    }
}

// ---------------------------------------------------------------------------
// Launch
// ---------------------------------------------------------------------------
extern "C" void kernel_launch(void* const* d_in, const int* in_sizes, int n_in,
                              void* d_out, int out_size)
{
    const float* q  = (const float*)d_in[0];
    const float* k  = (const float*)d_in[1];
    const float* v  = (const float*)d_in[2];
    const float* Wq = (const float*)d_in[3];
    const float* bq = (const float*)d_in[4];
    const float* Wk = (const float*)d_in[5];
    const float* bk = (const float*)d_in[6];
    const float* Wv = (const float*)d_in[7];
    const float* bv = (const float*)d_in[8];
    const float* Wo = (const float*)d_in[9];
    const float* bo = (const float*)d_in[10];
    float* out = (float*)d_out;

    __nv_bfloat16 *pA1hi, *pA1lo, *pA2hi, *pA2lo, *pA3hi, *pA3lo, *pWhi, *pWlo;
    __nv_bfloat16 *pQh, *pQl, *pKh, *pKl, *pVh, *pVl;
    cudaGetSymbolAddress((void**)&pA1hi, g_A1hi);
    cudaGetSymbolAddress((void**)&pA1lo, g_A1lo);
    cudaGetSymbolAddress((void**)&pA2hi, g_A2hi);
    cudaGetSymbolAddress((void**)&pA2lo, g_A2lo);
    cudaGetSymbolAddress((void**)&pA3hi, g_A3hi);
    cudaGetSymbolAddress((void**)&pA3lo, g_A3lo);
    cudaGetSymbolAddress((void**)&pWhi, g_Whi);
    cudaGetSymbolAddress((void**)&pWlo, g_Wlo);
    cudaGetSymbolAddress((void**)&pQh, g_Qhi);
    cudaGetSymbolAddress((void**)&pQl, g_Qlo);
    cudaGetSymbolAddress((void**)&pKh, g_Khi);
    cudaGetSymbolAddress((void**)&pKl, g_Klo);
    cudaGetSymbolAddress((void**)&pVh, g_Vhi);
    cudaGetSymbolAddress((void**)&pVl, g_Vlo);

    cudaFuncSetAttribute(gemm_qkv, cudaFuncAttributeMaxDynamicSharedMemorySize, GEMM_SMEM);
    cudaFuncSetAttribute(gemm_mma, cudaFuncAttributeMaxDynamicSharedMemorySize, GEMM_SMEM);
    cudaFuncSetAttribute(flash_mma, cudaFuncAttributeMaxDynamicSharedMemorySize, FLASH_SMEM);

    const float qscale = 0.125f * 1.4426950408889634f;   // 1/sqrt(dk) * log2(e)

    // 1) split all three activations (grid.y selects q/k/v)
    split3_act<<<dim3(512, 3), 256>>>(q, k, v,
                                      pA1hi, pA1lo, pA2hi, pA2lo, pA3hi, pA3lo,
                                      MROWS * DMODEL);
    // 2) split all four weights into slots 0..3 of g_Whi/g_Wlo
    split4_w<<<dim3(256, 4), 256>>>(Wq, Wk, Wv, Wo, pWhi, pWlo, DMODEL * DMODEL);

    // 3) fused QKV projection GEMM (grid.z selects)
    gemm_qkv<<<dim3(DMODEL / BN, MROWS / BM, 3), 256, GEMM_SMEM>>>(
        pA1hi, pA1lo, pA2hi, pA2lo, pA3hi, pA3lo, pWhi, pWlo,
        bq, bk, bv, pQh, pQl, pKh, pKl, pVh, pVl, qscale);

    // 4) flash attention -> O hi/lo into g_A1hi/g_A1lo
    flash_mma<<<dim3(SEQ / 128, HEADS, BATCH), 256, FLASH_SMEM>>>();

    // 5) output projection (Wo = slot 3)
    gemm_mma<<<dim3(DMODEL / BN, MROWS / BM), 256, GEMM_SMEM>>>(
        pA1hi, pA1lo,
        pWhi + (size_t)3 * DMODEL * DMODEL, pWlo + (size_t)3 * DMODEL * DMODEL,
        bo, out);
}